// round 13
// baseline (speedup 1.0000x reference)
#include <cuda_runtime.h>
#include <math.h>
#include <stdint.h>

#define HID     2048
#define KVD     512
#define HEADS   16
#define GROUPS  4
#define HDIM    128
#define BATCH   2
#define SEQ     2048
#define MROWS   (BATCH*SEQ)   // 4096

// ---------------- scratch (no cudaMalloc allowed) ----------------
__device__ float g_Q[(size_t)MROWS * HID];    // tf32, hdim cols pair-permuted (attn layout)
__device__ float g_K[(size_t)MROWS * KVD];    // tf32, hdim cols pair-permuted
__device__ float g_V[(size_t)MROWS * KVD];    // tf32, key rows pair-interleaved
__device__ float g_O[(size_t)MROWS * HID];    // tf32, k-dim pair-permuted (GEMM-A layout)
__device__ float g_Xt[(size_t)MROWS * HID];   // tf32 copy of X, k-dim pair-permuted
__device__ float g_Wqt[(size_t)HID * HID];    // weights: k-pair-interleaved tf32
__device__ float g_Wkt[(size_t)HID * KVD];
__device__ float g_Wvt[(size_t)HID * KVD];
__device__ float g_Wot[(size_t)HID * HID];

// ---------------- helpers ----------------
__device__ __forceinline__ unsigned f2tf(float x) {
    unsigned u;
    asm("cvt.rna.tf32.f32 %0, %1;" : "=r"(u) : "f"(x));
    return u;
}
__device__ __forceinline__ float tfs(float x) { return __uint_as_float(f2tf(x)); }
__device__ __forceinline__ unsigned uf(float x) { return __float_as_uint(x); }

// pair permutation within an 8-group: orig j -> stored position (j, j+4 adjacent)
__device__ __forceinline__ int pcol(int j) { return (j < 4) ? 2 * j : 2 * (j - 4) + 1; }

__device__ __forceinline__ void mma_tf32(float c[4], const unsigned a[4], const unsigned b[2]) {
    asm volatile(
        "mma.sync.aligned.m16n8k8.row.col.f32.tf32.tf32.f32 "
        "{%0,%1,%2,%3},{%4,%5,%6,%7},{%8,%9},{%0,%1,%2,%3};\n"
        : "+f"(c[0]), "+f"(c[1]), "+f"(c[2]), "+f"(c[3])
        : "r"(a[0]), "r"(a[1]), "r"(a[2]), "r"(a[3]), "r"(b[0]), "r"(b[1]));
}

__device__ __forceinline__ void cp_async16(void* smem, const void* gmem) {
    unsigned sa = (unsigned)__cvta_generic_to_shared(smem);
    asm volatile("cp.async.cg.shared.global [%0], [%1], 16;\n" :: "r"(sa), "l"(gmem));
}
#define CP_COMMIT asm volatile("cp.async.commit_group;\n")
#define CP_WAIT0  asm volatile("cp.async.wait_group 0;\n")

// ================= prep kernels =================
// A-side: tf32 + k-pair permutation within 8-groups
__global__ __launch_bounds__(256) void tf32_cast_perm(const float* __restrict__ in,
                                                      float* __restrict__ out, int n4)
{
    int i = blockIdx.x * 256 + threadIdx.x;
    if (i < n4) {
        float4 v = ((const float4*)in)[i];
        int f = i * 4;
        int base = f & ~7, j = f & 7;       // j in {0,4}
        out[base + pcol(j + 0)] = tfs(v.x);
        out[base + pcol(j + 1)] = tfs(v.y);
        out[base + pcol(j + 2)] = tfs(v.z);
        out[base + pcol(j + 3)] = tfs(v.w);
    }
}

// B-side: tf32 + k-row pair-interleave (rows k,k+4 element-interleaved, 2N-float lines)
// addr(k,n) = (k&~7)*N + (k&3)*2N + n*2 + ((k>>2)&1)
__global__ __launch_bounds__(256) void wkint(const float* __restrict__ in,
                                             float* __restrict__ out, int K, int N)
{
    int n4pr = N >> 2;
    int i = blockIdx.x * 256 + threadIdx.x;
    if (i < K * n4pr) {
        int k = i / n4pr, n4 = i - k * n4pr;
        float4 v = *(const float4*)(in + (size_t)k * N + n4 * 4);
        size_t base = (size_t)(k & ~7) * N + (size_t)(k & 3) * 2 * N + ((k >> 2) & 1);
        out[base + (size_t)(n4 * 4 + 0) * 2] = tfs(v.x);
        out[base + (size_t)(n4 * 4 + 1) * 2] = tfs(v.y);
        out[base + (size_t)(n4 * 4 + 2) * 2] = tfs(v.z);
        out[base + (size_t)(n4 * 4 + 3) * 2] = tfs(v.w);
    }
}

// ================= GEMM (tf32 tensor cores): C[M,N] = A[M,K]@W[K,N] + bias ===========
// A: k-pair-permuted [M][K]. W: k-pair-interleaved. All fragment gathers LDS.64,
// conflict-free (As pad 40: 20=4 mod 16; Bs line 264: 132=4 mod 16).
// EPI: 0 plain fp32; 1 tf32 + col pair-permute (Q,K); 2 tf32 + V row interleave.
#define GBK 32
#define G_AS (128*40)
#define G_BS (16*264)
#define GSMEM ((2*G_AS + 2*G_BS) * 4)   // 74752 B -> 2 CTAs/SM

template<int EPI>
__device__ __forceinline__ void gemm_body(
    const float* __restrict__ A, const float* __restrict__ W,
    const float* __restrict__ bias, float* __restrict__ C,
    int M, int N, int K, int bm, int bn, float* gsm)
{
    float (*As)[128][40]  = (float(*)[128][40])gsm;
    float (*Bs)[16][264]  = (float(*)[16][264])(gsm + 2 * G_AS);

    const int tid = threadIdx.x;
    const int lane = tid & 31, wid = tid >> 5;
    const int gid = lane >> 2, tig = lane & 3;
    const int wm = wid >> 1, wn = wid & 1;

    float acc[2][8][4];
#pragma unroll
    for (int i = 0; i < 2; i++)
#pragma unroll
        for (int j = 0; j < 8; j++)
#pragma unroll
            for (int v = 0; v < 4; v++) acc[i][j][v] = 0.f;

    const int T = K / GBK;

    auto load_stage = [&](int st, int t) {
        const int k0 = t * GBK;
#pragma unroll
        for (int u = 0; u < 4; u++) {
            int id = tid + u * 256;
            // A: 128 rows x 8 chunks (k-pair-permuted rows, contiguous 128B)
            int ra = id >> 3, ca = id & 7;
            cp_async16(&As[st][ra][ca * 4],
                       A + (size_t)(bm + ra) * K + k0 + ca * 4);
            // B: 16 pair-lines x 64 chunks; line l holds rows (k0+8*(l>>2)+(l&3), +4)
            int line = id >> 6, cc = id & 63;
            const float* src = W + (size_t)(k0 + (line >> 2) * 8) * N
                             + (size_t)(line & 3) * 2 * N + (size_t)bn * 2 + cc * 4;
            cp_async16(&Bs[st][line][cc * 4], src);
        }
    };

    load_stage(0, 0);
    CP_COMMIT;

    for (int t = 0; t < T; t++) {
        const int st = t & 1;
        CP_WAIT0;
        __syncthreads();
        if (t + 1 < T) {
            load_stage(st ^ 1, t + 1);
            CP_COMMIT;
        }

#pragma unroll
        for (int kk = 0; kk < GBK; kk += 8) {
            unsigned a[2][4];
#pragma unroll
            for (int mt = 0; mt < 2; mt++) {
                int r = wm * 32 + mt * 16 + gid;
                float2 a0 = *(const float2*)&As[st][r][kk + 2 * tig];
                float2 a1 = *(const float2*)&As[st][r + 8][kk + 2 * tig];
                a[mt][0] = uf(a0.x); a[mt][1] = uf(a1.x);
                a[mt][2] = uf(a0.y); a[mt][3] = uf(a1.y);
            }
            const int kp = kk / 2 + tig;    // pair-line: rows (kk+tig, kk+tig+4)
#pragma unroll
            for (int nt = 0; nt < 8; nt++) {
                int c = wn * 64 + nt * 8 + gid;
                float2 bv = *(const float2*)&Bs[st][kp][c * 2];
                unsigned bf[2] = {uf(bv.x), uf(bv.y)};
                mma_tf32(acc[0][nt], a[0], bf);
                mma_tf32(acc[1][nt], a[1], bf);
            }
        }
    }

    // epilogue
    const int pj0 = pcol(2 * tig), pj1 = pcol(2 * tig + 1);
#pragma unroll
    for (int mt = 0; mt < 2; mt++) {
        int rbase = bm + wm * 32 + mt * 16 + gid;
#pragma unroll
        for (int nt = 0; nt < 8; nt++) {
            int cb = bn + wn * 64 + nt * 8;
            int c = cb + 2 * tig;
            float bx = bias[c], by = bias[c + 1];
            float v0 = acc[mt][nt][0] + bx, v1 = acc[mt][nt][1] + by;
            float v2 = acc[mt][nt][2] + bx, v3 = acc[mt][nt][3] + by;
            if (EPI == 0) {
                *(float2*)&C[(size_t)rbase * N + c] = make_float2(v0, v1);
                *(float2*)&C[(size_t)(rbase + 8) * N + c] = make_float2(v2, v3);
            } else if (EPI == 1) {
                C[(size_t)rbase * N + cb + pj0] = tfs(v0);
                C[(size_t)rbase * N + cb + pj1] = tfs(v1);
                C[(size_t)(rbase + 8) * N + cb + pj0] = tfs(v2);
                C[(size_t)(rbase + 8) * N + cb + pj1] = tfs(v3);
            } else {
                // V: row pair-interleave addr(r,c) = (r&~7)*N + (r&3)*2N + c*2 + ((r>>2)&1)
#pragma unroll
                for (int rr = 0; rr < 2; rr++) {
                    int r = rbase + rr * 8;
                    size_t base = (size_t)(r & ~7) * N + (size_t)(r & 3) * 2 * N + ((r >> 2) & 1);
                    float a0 = rr ? v2 : v0, a1 = rr ? v3 : v1;
                    C[base + (size_t)c * 2] = tfs(a0);
                    C[base + (size_t)(c + 1) * 2] = tfs(a1);
                }
            }
        }
    }
}

template<int EPI>
__global__ __launch_bounds__(256, 2) void gemm_mma(
    const float* __restrict__ A, const float* __restrict__ W,
    const float* __restrict__ bias, float* __restrict__ C,
    int M, int N, int K)
{
    extern __shared__ float gsm[];
    gemm_body<EPI>(A, W, bias, C, M, N, K,
                   blockIdx.y * 128, blockIdx.x * 128, gsm);
}

// fused K+V projection: grid.x = 8; bx<4 -> K (EPI1), else V (EPI2)
__global__ __launch_bounds__(256, 2) void gemm_mma_kv(
    const float* __restrict__ A,
    const float* __restrict__ Wk, const float* __restrict__ Wv,
    const float* __restrict__ bk, const float* __restrict__ bv,
    float* __restrict__ Ck, float* __restrict__ Cv,
    int M, int K)
{
    extern __shared__ float gsm[];
    const bool isK = blockIdx.x < 4;
    const int bn = (blockIdx.x & 3) * 128;
    const int bm = blockIdx.y * 128;
    if (isK)
        gemm_body<1>(A, Wk, bk, Ck, M, KVD, K, bm, bn, gsm);
    else
        gemm_body<2>(A, Wv, bv, Cv, M, KVD, K, bm, bn, gsm);
}

// ================= Flash attention on tensor cores (R11, O epilogue permuted) ==========
#define AQP 136
#define AKP 136
#define AVL 264
#define APP 40
#define OQ_  0
#define OKs  (64*AQP)
#define OVs  (OKs + 2*32*AKP)
#define OPs  (OVs + 2*16*AVL)
#define OMs  (OPs + 64*APP)
#define ASMEM ((OMs + 2*32) * 4)       // 113920 B -> 2 CTAs/SM

__global__ __launch_bounds__(128, 2) void attn_mma(const int* __restrict__ mask)
{
    extern __shared__ float sm[];
    float (*Qs)[AQP]     = (float(*)[AQP])(sm + OQ_);
    float (*Ks)[32][AKP] = (float(*)[32][AKP])(sm + OKs);
    float (*Vs)[16][AVL] = (float(*)[16][AVL])(sm + OVs);
    float (*Ps)[APP]     = (float(*)[APP])(sm + OPs);
    int (*Ms)[32]        = (int(*)[32])(sm + OMs);

    const int tid = threadIdx.x;
    const int w = tid >> 5, lane = tid & 31;
    const int gid = lane >> 2, tig = lane & 3;
    const int qt = blockIdx.x, h = blockIdx.y, b = blockIdx.z;
    const int g = h % GROUPS;
    const int q0 = qt * 64;

    const float scale = 0.08838834764831845f;  // 1/sqrt(128)
    const float* Qg = g_Q + (size_t)(b * SEQ + q0) * HID + h * HDIM;
    const float* Kg0 = g_K + (size_t)(b * SEQ) * KVD + g * HDIM;
    const float* Vg0 = g_V + (size_t)(b * SEQ) * KVD;
    const int*   Mg0 = mask + b * SEQ;

    auto issue_kv = [&](int st, int kt) {
        const int k0 = kt * 32;
#pragma unroll
        for (int u = 0; u < 8; u++) {
            int id = tid + u * 128;
            int r = id >> 5, c4 = id & 31;
            cp_async16(&Ks[st][r][c4 * 4], Kg0 + (size_t)(k0 + r) * KVD + c4 * 4);
            int line = id >> 6, cc = id & 63;
            const float* src = Vg0 + (size_t)(k0 + (line >> 2) * 8) * KVD
                             + (size_t)(line & 3) * 2 * KVD + g * HDIM * 2 + cc * 4;
            cp_async16(&Vs[st][line][cc * 4], src);
        }
        if (tid < 8) cp_async16(&Ms[st][tid * 4], Mg0 + k0 + tid * 4);
    };

    issue_kv(0, 0);
    CP_COMMIT;

    // Q prologue: straight copy (already col-permuted + tf32), scale + re-round
#pragma unroll
    for (int u = 0; u < 16; u++) {
        int idx = tid + u * 128;
        int r = idx >> 5, c4 = idx & 31;
        float4 v = *(const float4*)(Qg + (size_t)r * HID + c4 * 4);
        float4 o = make_float4(tfs(v.x * scale), tfs(v.y * scale),
                               tfs(v.z * scale), tfs(v.w * scale));
        *(float4*)&Qs[r][c4 * 4] = o;
    }

    float m_run[2] = {-1e30f, -1e30f};
    float l_run[2] = {0.f, 0.f};
    float o_acc[16][4];
#pragma unroll
    for (int nt = 0; nt < 16; nt++)
#pragma unroll
        for (int v = 0; v < 4; v++) o_acc[nt][v] = 0.f;

    const int r = w * 16 + gid;
    const int pj0 = pcol(2 * tig), pj1 = pcol(2 * tig + 1);

    for (int kt = 0; kt < SEQ / 32; kt++) {
        const int st = kt & 1;
        CP_WAIT0;
        __syncthreads();
        if (kt + 1 < SEQ / 32) {
            issue_kv(st ^ 1, kt + 1);
            CP_COMMIT;
        }

        // ---- S = Q @ K^T (conflict-free LDS.64 gathers) ----
        float s[4][4];
#pragma unroll
        for (int nt = 0; nt < 4; nt++)
#pragma unroll
            for (int v = 0; v < 4; v++) s[nt][v] = 0.f;

#pragma unroll
        for (int ks = 0; ks < 16; ks++) {
            const int kk = ks * 8;
            float2 q0 = *(const float2*)&Qs[r][kk + 2 * tig];
            float2 q1 = *(const float2*)&Qs[r + 8][kk + 2 * tig];
            unsigned qa[4] = {uf(q0.x), uf(q1.x), uf(q0.y), uf(q1.y)};
#pragma unroll
            for (int nt = 0; nt < 4; nt++) {
                float2 kv = *(const float2*)&Ks[st][nt * 8 + gid][kk + 2 * tig];
                unsigned kb[2] = {uf(kv.x), uf(kv.y)};
                mma_tf32(s[nt], qa, kb);
            }
        }

        // ---- mask ----
#pragma unroll
        for (int nt = 0; nt < 4; nt++) {
            int c = nt * 8 + 2 * tig;
            if (Ms[st][c] == 0)     { s[nt][0] = -1e30f; s[nt][2] = -1e30f; }
            if (Ms[st][c + 1] == 0) { s[nt][1] = -1e30f; s[nt][3] = -1e30f; }
        }

        // ---- online softmax ----
#pragma unroll
        for (int hh = 0; hh < 2; hh++) {
            float mx = -1e30f;
#pragma unroll
            for (int nt = 0; nt < 4; nt++)
                mx = fmaxf(mx, fmaxf(s[nt][2 * hh], s[nt][2 * hh + 1]));
            mx = fmaxf(mx, __shfl_xor_sync(0xffffffffu, mx, 1));
            mx = fmaxf(mx, __shfl_xor_sync(0xffffffffu, mx, 2));
            float mnew = fmaxf(m_run[hh], mx);
            float corr = __expf(m_run[hh] - mnew);
            float sum = 0.f;
#pragma unroll
            for (int nt = 0; nt < 4; nt++) {
                float p0 = __expf(s[nt][2 * hh] - mnew);
                float p1 = __expf(s[nt][2 * hh + 1] - mnew);
                s[nt][2 * hh] = p0; s[nt][2 * hh + 1] = p1;
                sum += p0 + p1;
            }
            sum += __shfl_xor_sync(0xffffffffu, sum, 1);
            sum += __shfl_xor_sync(0xffffffffu, sum, 2);
            l_run[hh] = l_run[hh] * corr + sum;
            if (mnew > m_run[hh]) {
                m_run[hh] = mnew;
#pragma unroll
                for (int nt = 0; nt < 16; nt++) {
                    o_acc[nt][2 * hh] *= corr;
                    o_acc[nt][2 * hh + 1] *= corr;
                }
            }
        }

        // ---- store P (key-col pair permuted, matches V interleave) ----
#pragma unroll
        for (int nt = 0; nt < 4; nt++) {
            int cb = nt * 8;
            Ps[r][cb + pj0] = tfs(s[nt][0]);
            Ps[r][cb + pj1] = tfs(s[nt][1]);
            Ps[r + 8][cb + pj0] = tfs(s[nt][2]);
            Ps[r + 8][cb + pj1] = tfs(s[nt][3]);
        }
        __syncwarp();

        // ---- O += P @ V ----
#pragma unroll
        for (int ks = 0; ks < 4; ks++) {
            const int kk = ks * 8;
            float2 p0 = *(const float2*)&Ps[r][kk + 2 * tig];
            float2 p1 = *(const float2*)&Ps[r + 8][kk + 2 * tig];
            unsigned pa[4] = {uf(p0.x), uf(p1.x), uf(p0.y), uf(p1.y)};
            const int kp = kk / 2 + tig;
#pragma unroll
            for (int nt = 0; nt < 16; nt++) {
                float2 vv = *(const float2*)&Vs[st][kp][(nt * 8 + gid) * 2];
                unsigned vb[2] = {uf(vv.x), uf(vv.y)};
                mma_tf32(o_acc[nt], pa, vb);
            }
        }
    }

    // ---- epilogue: O /= l, tf32-rounded, k-pair-permuted for the out-proj GEMM ----
    float* Og = g_O + (size_t)(b * SEQ + q0) * HID + h * HDIM;
    const float i0 = 1.f / l_run[0], i1 = 1.f / l_run[1];
#pragma unroll
    for (int nt = 0; nt < 16; nt++) {
        int cb = nt * 8;
        Og[(size_t)r * HID + cb + pj0] = tfs(o_acc[nt][0] * i0);
        Og[(size_t)r * HID + cb + pj1] = tfs(o_acc[nt][1] * i0);
        Og[(size_t)(r + 8) * HID + cb + pj0] = tfs(o_acc[nt][2] * i1);
        Og[(size_t)(r + 8) * HID + cb + pj1] = tfs(o_acc[nt][3] * i1);
    }
}

// ================= launch =================
extern "C" void kernel_launch(void* const* d_in, const int* in_sizes, int n_in,
                              void* d_out, int out_size)
{
    const float* X    = (const float*)d_in[0];
    const int*   mask = (const int*)  d_in[1];
    const float* Wq   = (const float*)d_in[2];
    const float* bq   = (const float*)d_in[3];
    const float* Wk   = (const float*)d_in[4];
    const float* bk   = (const float*)d_in[5];
    const float* Wv   = (const float*)d_in[6];
    const float* bv   = (const float*)d_in[7];
    const float* Wo   = (const float*)d_in[8];
    const float* bo   = (const float*)d_in[9];
    float* out = (float*)d_out;

    float *Qp, *Kp, *Vp, *Op, *Xt, *Wqt, *Wkt, *Wvt, *Wot;
    cudaGetSymbolAddress((void**)&Qp, g_Q);
    cudaGetSymbolAddress((void**)&Kp, g_K);
    cudaGetSymbolAddress((void**)&Vp, g_V);
    cudaGetSymbolAddress((void**)&Op, g_O);
    cudaGetSymbolAddress((void**)&Xt, g_Xt);
    cudaGetSymbolAddress((void**)&Wqt, g_Wqt);
    cudaGetSymbolAddress((void**)&Wkt, g_Wkt);
    cudaGetSymbolAddress((void**)&Wvt, g_Wvt);
    cudaGetSymbolAddress((void**)&Wot, g_Wot);

    cudaFuncSetAttribute(gemm_mma<0>, cudaFuncAttributeMaxDynamicSharedMemorySize, GSMEM);
    cudaFuncSetAttribute(gemm_mma<1>, cudaFuncAttributeMaxDynamicSharedMemorySize, GSMEM);
    cudaFuncSetAttribute(gemm_mma_kv, cudaFuncAttributeMaxDynamicSharedMemorySize, GSMEM);
    cudaFuncSetAttribute(attn_mma, cudaFuncAttributeMaxDynamicSharedMemorySize, ASMEM);

    // prep: Xt k-pair-permuted tf32; weights k-pair-interleaved tf32
    {
        int nX = MROWS * HID / 4;
        tf32_cast_perm<<<(nX + 255) / 256, 256>>>(X, Xt, nX);
        int nQ = HID * HID / 4, nK = HID * KVD / 4;
        wkint<<<(nQ + 255) / 256, 256>>>(Wq, Wqt, HID, HID);
        wkint<<<(nK + 255) / 256, 256>>>(Wk, Wkt, HID, KVD);
        wkint<<<(nK + 255) / 256, 256>>>(Wv, Wvt, HID, KVD);
        wkint<<<(nQ + 255) / 256, 256>>>(Wo, Wot, HID, HID);
    }

    dim3 blk(256);
    gemm_mma<1><<<dim3(HID / 128, MROWS / 128), blk, GSMEM>>>(Xt, Wqt, bq, Qp, MROWS, HID, HID);
    gemm_mma_kv<<<dim3(8, MROWS / 128), blk, GSMEM>>>(Xt, Wkt, Wvt, bk, bv, Kp, Vp, MROWS, HID);

    attn_mma<<<dim3(SEQ / 64, HEADS, BATCH), dim3(128), ASMEM>>>(mask);

    gemm_mma<0><<<dim3(HID / 128, MROWS / 128), blk, GSMEM>>>(Op, Wot, bo, out, MROWS, HID, HID);
}

// round 14
// speedup vs baseline: 2.0741x; 2.0741x over previous
#include <cuda_runtime.h>
#include <cuda_fp16.h>
#include <math.h>
#include <stdint.h>

#define HID     2048
#define KVD     512
#define HEADS   16
#define GROUPS  4
#define HDIM    128
#define BATCH   2
#define SEQ     2048
#define MROWS   (BATCH*SEQ)   // 4096

// ---------------- scratch (no cudaMalloc allowed) ----------------
__device__ __half g_Q[(size_t)MROWS * HID];    // half, plain [row][dim]
__device__ __half g_K[(size_t)MROWS * KVD];    // half, plain [row][dim]
__device__ __half g_V[(size_t)MROWS * KVD];    // half, key-pair interleaved
__device__ __half g_O[(size_t)MROWS * HID];    // half, plain
__device__ __half g_Xh[(size_t)MROWS * HID];   // half copy of X
__device__ __half g_Wqt[(size_t)HID * HID];    // W^T [N][K] half
__device__ __half g_Wkt[(size_t)KVD * HID];
__device__ __half g_Wvt[(size_t)KVD * HID];
__device__ __half g_Wot[(size_t)HID * HID];

// ---------------- helpers ----------------
__device__ __forceinline__ void mma_f16(float c[4], const unsigned a[4],
                                        unsigned b0, unsigned b1) {
    asm volatile(
        "mma.sync.aligned.m16n8k16.row.col.f32.f16.f16.f32 "
        "{%0,%1,%2,%3},{%4,%5,%6,%7},{%8,%9},{%0,%1,%2,%3};\n"
        : "+f"(c[0]), "+f"(c[1]), "+f"(c[2]), "+f"(c[3])
        : "r"(a[0]), "r"(a[1]), "r"(a[2]), "r"(a[3]), "r"(b0), "r"(b1));
}

__device__ __forceinline__ void cp_async16(void* smem, const void* gmem) {
    unsigned sa = (unsigned)__cvta_generic_to_shared(smem);
    asm volatile("cp.async.cg.shared.global [%0], [%1], 16;\n" :: "r"(sa), "l"(gmem));
}
#define CP_COMMIT asm volatile("cp.async.commit_group;\n")
#define CP_WAIT0  asm volatile("cp.async.wait_group 0;\n")

__device__ __forceinline__ unsigned ldu32(const __half* p) {
    return *(const unsigned*)p;
}

// ================= prep kernels =================
// fp32 -> fp16 cast, 8 elements per thread
__global__ __launch_bounds__(256) void h_cast(const float* __restrict__ in,
                                              __half* __restrict__ out, int n8)
{
    int i = blockIdx.x * 256 + threadIdx.x;
    if (i < n8) {
        float4 v0 = ((const float4*)in)[2 * i];
        float4 v1 = ((const float4*)in)[2 * i + 1];
        __half2 o[4];
        o[0] = __floats2half2_rn(v0.x, v0.y);
        o[1] = __floats2half2_rn(v0.z, v0.w);
        o[2] = __floats2half2_rn(v1.x, v1.y);
        o[3] = __floats2half2_rn(v1.z, v1.w);
        *(uint4*)&out[8 * i] = *(uint4*)o;
    }
}

// W [K][N] fp32 -> Wt [N][K] fp16
__global__ __launch_bounds__(256) void wtrans_h(const float* __restrict__ in,
                                                __half* __restrict__ out, int K, int N)
{
    __shared__ float t[32][33];
    const int k0 = blockIdx.x * 32, n0 = blockIdx.y * 32;
    const int tx = threadIdx.x & 31, ty = threadIdx.x >> 5;
#pragma unroll
    for (int u = 0; u < 4; u++)
        t[ty + u * 8][tx] = in[(size_t)(k0 + ty + u * 8) * N + n0 + tx];
    __syncthreads();
#pragma unroll
    for (int u = 0; u < 4; u++)
        out[(size_t)(n0 + ty + u * 8) * K + k0 + tx] = __float2half(t[tx][ty + u * 8]);
}

// ================= GEMM (fp16 tensor cores): C[M,N] = A[M,K]@W[K,N] + bias ===========
// A [M][K] half, Bt [N][K] half. 128x128x64 tile, 256 threads = 8 warps (4x2).
// Smem rows padded to 72 halves (36 words = 4 mod 8 -> conflict-free LDS.32).
// EPI: 0 plain fp32 out; 1 half plain (Q,K); 2 half key-pair interleaved (V).
#define GBK 64
#define BKP 72
#define G_TILE (128*BKP)            // halves per tile
#define GSMEM (4*G_TILE*2)          // 73728 B (2 stages x A,B)

template<int EPI>
__device__ __forceinline__ void gemm_body(
    const __half* __restrict__ A, const __half* __restrict__ Bt,
    const float* __restrict__ bias, void* Cptr,
    int M, int N, int K, int bm, int bn, __half* gsm)
{
    __half (*As)[128][BKP] = (__half(*)[128][BKP])gsm;
    __half (*Bs)[128][BKP] = (__half(*)[128][BKP])(gsm + 2 * G_TILE);

    const int tid = threadIdx.x;
    const int lane = tid & 31, wid = tid >> 5;
    const int gid = lane >> 2, tig = lane & 3;
    const int wm = wid >> 1, wn = wid & 1;

    float acc[2][8][4];
#pragma unroll
    for (int i = 0; i < 2; i++)
#pragma unroll
        for (int j = 0; j < 8; j++)
#pragma unroll
            for (int v = 0; v < 4; v++) acc[i][j][v] = 0.f;

    const int T = K / GBK;

    auto load_stage = [&](int st, int t) {
        const int k0 = t * GBK;
#pragma unroll
        for (int u = 0; u < 4; u++) {
            int id = tid + u * 256;              // 0..1023
            int r = id >> 3, c = id & 7;         // 8 chunks of 8 halves per row
            cp_async16(&As[st][r][c * 8], A  + (size_t)(bm + r) * K + k0 + c * 8);
            cp_async16(&Bs[st][r][c * 8], Bt + (size_t)(bn + r) * K + k0 + c * 8);
        }
    };

    load_stage(0, 0);
    CP_COMMIT;

    for (int t = 0; t < T; t++) {
        const int st = t & 1;
        CP_WAIT0;
        __syncthreads();
        if (t + 1 < T) {
            load_stage(st ^ 1, t + 1);
            CP_COMMIT;
        }

#pragma unroll
        for (int kk = 0; kk < GBK; kk += 16) {
            unsigned a[2][4];
#pragma unroll
            for (int mt = 0; mt < 2; mt++) {
                int r = wm * 32 + mt * 16 + gid;
                a[mt][0] = ldu32(&As[st][r][kk + 2 * tig]);
                a[mt][1] = ldu32(&As[st][r + 8][kk + 2 * tig]);
                a[mt][2] = ldu32(&As[st][r][kk + 2 * tig + 8]);
                a[mt][3] = ldu32(&As[st][r + 8][kk + 2 * tig + 8]);
            }
#pragma unroll
            for (int nt = 0; nt < 8; nt++) {
                int c = wn * 64 + nt * 8 + gid;
                unsigned b0 = ldu32(&Bs[st][c][kk + 2 * tig]);
                unsigned b1 = ldu32(&Bs[st][c][kk + 2 * tig + 8]);
                mma_f16(acc[0][nt], a[0], b0, b1);
                mma_f16(acc[1][nt], a[1], b0, b1);
            }
        }
    }

    // epilogue
#pragma unroll
    for (int mt = 0; mt < 2; mt++) {
        int rbase = bm + wm * 32 + mt * 16 + gid;
#pragma unroll
        for (int nt = 0; nt < 8; nt++) {
            int c = bn + wn * 64 + nt * 8 + 2 * tig;
            float bx = bias[c], by = bias[c + 1];
            float v0 = acc[mt][nt][0] + bx, v1 = acc[mt][nt][1] + by;
            float v2 = acc[mt][nt][2] + bx, v3 = acc[mt][nt][3] + by;
            if (EPI == 0) {
                float* C = (float*)Cptr;
                *(float2*)&C[(size_t)rbase * N + c] = make_float2(v0, v1);
                *(float2*)&C[(size_t)(rbase + 8) * N + c] = make_float2(v2, v3);
            } else if (EPI == 1) {
                __half* C = (__half*)Cptr;
                *(__half2*)&C[(size_t)rbase * N + c] = __floats2half2_rn(v0, v1);
                *(__half2*)&C[(size_t)(rbase + 8) * N + c] = __floats2half2_rn(v2, v3);
            } else {
                // V: key-pair interleave addr(r,c) = (r&~1)*N + c*2 + (r&1)
                __half* C = (__half*)Cptr;
#pragma unroll
                for (int rr = 0; rr < 2; rr++) {
                    int r = rbase + rr * 8;
                    size_t base = (size_t)(r & ~1) * N + (r & 1);
                    float a0 = rr ? v2 : v0, a1 = rr ? v3 : v1;
                    C[base + (size_t)c * 2] = __float2half(a0);
                    C[base + (size_t)(c + 1) * 2] = __float2half(a1);
                }
            }
        }
    }
}

template<int EPI>
__global__ __launch_bounds__(256, 2) void gemm_h(
    const __half* __restrict__ A, const __half* __restrict__ Bt,
    const float* __restrict__ bias, void* C, int M, int N, int K)
{
    extern __shared__ __half gsm[];
    gemm_body<EPI>(A, Bt, bias, C, M, N, K,
                   blockIdx.y * 128, blockIdx.x * 128, gsm);
}

// fused K+V projection: grid.x = 8; bx<4 -> K (EPI1), else V (EPI2)
__global__ __launch_bounds__(256, 2) void gemm_h_kv(
    const __half* __restrict__ A,
    const __half* __restrict__ Wk, const __half* __restrict__ Wv,
    const float* __restrict__ bk, const float* __restrict__ bv,
    __half* __restrict__ Ck, __half* __restrict__ Cv, int M, int K)
{
    extern __shared__ __half gsm[];
    const bool isK = blockIdx.x < 4;
    const int bn = (blockIdx.x & 3) * 128;
    const int bm = blockIdx.y * 128;
    if (isK)
        gemm_body<1>(A, Wk, bk, (void*)Ck, M, KVD, K, bm, bn, gsm);
    else
        gemm_body<2>(A, Wv, bv, (void*)Cv, M, KVD, K, bm, bn, gsm);
}

// ================= Flash attention (fp16 tensor cores) =================
// 128 threads = 4 warps (warp owns 16 Q rows), Q tile 64x128, K/V tiles 32 keys,
// double-buffered cp.async, 2 CTAs/SM. All frag loads LDS.32, conflict-free
// (row-words = 4 mod 8; V lines 136 words = 8 mod 32).
#define AQP 136                        // halves (68 words = 4 mod 8)
#define AKP 136
#define AVL 272                        // V line: 256 halves + 16 pad (136 words)
#define APP 40                         // 20 words = 4 mod 8
#define OQ_  0
#define OKs  (64*AQP)                  // 8704 halves
#define OVs  (OKs + 2*32*AKP)          // +8704
#define OPs  (OVs + 2*16*AVL)          // +8704
#define OMs  (OPs + 64*APP)            // +2560 -> 28672 halves
#define ASMEM (OMs*2 + 2*32*4)         // 57600 B -> 2 CTAs/SM

__global__ __launch_bounds__(128, 2) void attn_h(const int* __restrict__ mask)
{
    extern __shared__ __half sm[];
    __half (*Qs)[AQP]     = (__half(*)[AQP])(sm + OQ_);
    __half (*Ks)[32][AKP] = (__half(*)[32][AKP])(sm + OKs);
    __half (*Vs)[16][AVL] = (__half(*)[16][AVL])(sm + OVs);
    __half (*Ps)[APP]     = (__half(*)[APP])(sm + OPs);
    int (*Ms)[32]         = (int(*)[32])(sm + OMs);

    const int tid = threadIdx.x;
    const int w = tid >> 5, lane = tid & 31;
    const int gid = lane >> 2, tig = lane & 3;
    const int qt = blockIdx.x, h = blockIdx.y, b = blockIdx.z;
    const int g = h % GROUPS;
    const int q0 = qt * 64;

    const float scale = 0.08838834764831845f;  // 1/sqrt(128)
    const __half* Qg = g_Q + (size_t)(b * SEQ + q0) * HID + h * HDIM;
    const __half* Kg0 = g_K + (size_t)(b * SEQ) * KVD + g * HDIM;
    const __half* Vg0 = g_V + (size_t)(b * SEQ) * KVD;   // interleaved
    const int*    Mg0 = mask + b * SEQ;

    auto issue_kv = [&](int st, int kt) {
        const int k0 = kt * 32;
#pragma unroll
        for (int u = 0; u < 4; u++) {
            int id = tid + u * 128;              // 0..511
            // K: 32 rows x 16 chunks of 8 halves
            int r = id >> 4, c = id & 15;
            cp_async16(&Ks[st][r][c * 8], Kg0 + (size_t)(k0 + r) * KVD + c * 8);
            // V: 16 lines x 32 chunks; line t = keys (k0+2t, k0+2t+1) interleaved
            int line = id >> 5, cc = id & 31;
            const __half* src = Vg0 + (size_t)(k0 + 2 * line) * KVD + g * 256 + cc * 8;
            cp_async16(&Vs[st][line][cc * 8], src);
        }
        if (tid < 8) cp_async16(&Ms[st][tid * 4], Mg0 + k0 + tid * 4);
    };

    issue_kv(0, 0);
    CP_COMMIT;

    // Q prologue: load half, scale in fp32, re-round to half
#pragma unroll
    for (int u = 0; u < 8; u++) {
        int idx = tid + u * 128;                 // 0..1023 chunks
        int r = idx >> 4, c8 = idx & 15;
        uint4 raw = *(const uint4*)(Qg + (size_t)r * HID + c8 * 8);
        __half2* hp = (__half2*)&raw;
        __half2 o[4];
#pragma unroll
        for (int j = 0; j < 4; j++) {
            float2 f = __half22float2(hp[j]);
            o[j] = __floats2half2_rn(f.x * scale, f.y * scale);
        }
        *(uint4*)&Qs[r][c8 * 8] = *(uint4*)o;
    }

    float m_run[2] = {-1e30f, -1e30f};
    float l_run[2] = {0.f, 0.f};
    float o_acc[16][4];
#pragma unroll
    for (int nt = 0; nt < 16; nt++)
#pragma unroll
        for (int v = 0; v < 4; v++) o_acc[nt][v] = 0.f;

    const int r = w * 16 + gid;

    for (int kt = 0; kt < SEQ / 32; kt++) {
        const int st = kt & 1;
        CP_WAIT0;
        __syncthreads();
        if (kt + 1 < SEQ / 32) {
            issue_kv(st ^ 1, kt + 1);
            CP_COMMIT;
        }

        // ---- S = Q @ K^T (16 rows x 32 keys per warp) ----
        float s[4][4];
#pragma unroll
        for (int nt = 0; nt < 4; nt++)
#pragma unroll
            for (int v = 0; v < 4; v++) s[nt][v] = 0.f;

#pragma unroll
        for (int ks = 0; ks < 8; ks++) {
            const int kk = ks * 16;
            unsigned qa[4];
            qa[0] = ldu32(&Qs[r][kk + 2 * tig]);
            qa[1] = ldu32(&Qs[r + 8][kk + 2 * tig]);
            qa[2] = ldu32(&Qs[r][kk + 2 * tig + 8]);
            qa[3] = ldu32(&Qs[r + 8][kk + 2 * tig + 8]);
#pragma unroll
            for (int nt = 0; nt < 4; nt++) {
                int key = nt * 8 + gid;
                unsigned b0 = ldu32(&Ks[st][key][kk + 2 * tig]);
                unsigned b1 = ldu32(&Ks[st][key][kk + 2 * tig + 8]);
                mma_f16(s[nt], qa, b0, b1);
            }
        }

        // ---- mask ----
#pragma unroll
        for (int nt = 0; nt < 4; nt++) {
            int c = nt * 8 + 2 * tig;
            if (Ms[st][c] == 0)     { s[nt][0] = -1e30f; s[nt][2] = -1e30f; }
            if (Ms[st][c + 1] == 0) { s[nt][1] = -1e30f; s[nt][3] = -1e30f; }
        }

        // ---- online softmax (row halves gid, gid+8) ----
#pragma unroll
        for (int hh = 0; hh < 2; hh++) {
            float mx = -1e30f;
#pragma unroll
            for (int nt = 0; nt < 4; nt++)
                mx = fmaxf(mx, fmaxf(s[nt][2 * hh], s[nt][2 * hh + 1]));
            mx = fmaxf(mx, __shfl_xor_sync(0xffffffffu, mx, 1));
            mx = fmaxf(mx, __shfl_xor_sync(0xffffffffu, mx, 2));
            float mnew = fmaxf(m_run[hh], mx);
            float corr = __expf(m_run[hh] - mnew);
            float sum = 0.f;
#pragma unroll
            for (int nt = 0; nt < 4; nt++) {
                float p0 = __expf(s[nt][2 * hh] - mnew);
                float p1 = __expf(s[nt][2 * hh + 1] - mnew);
                s[nt][2 * hh] = p0; s[nt][2 * hh + 1] = p1;
                sum += p0 + p1;
            }
            sum += __shfl_xor_sync(0xffffffffu, sum, 1);
            sum += __shfl_xor_sync(0xffffffffu, sum, 2);
            l_run[hh] = l_run[hh] * corr + sum;
            if (mnew > m_run[hh]) {
                m_run[hh] = mnew;
#pragma unroll
                for (int nt = 0; nt < 16; nt++) {
                    o_acc[nt][2 * hh] *= corr;
                    o_acc[nt][2 * hh + 1] *= corr;
                }
            }
        }

        // ---- store P as half2 (natural adjacency, no permutation) ----
#pragma unroll
        for (int nt = 0; nt < 4; nt++) {
            int c = nt * 8 + 2 * tig;
            *(__half2*)&Ps[r][c]     = __floats2half2_rn(s[nt][0], s[nt][1]);
            *(__half2*)&Ps[r + 8][c] = __floats2half2_rn(s[nt][2], s[nt][3]);
        }
        __syncwarp();

        // ---- O += P @ V (V key-pair interleaved) ----
#pragma unroll
        for (int ks = 0; ks < 2; ks++) {
            const int kk = ks * 16;
            unsigned pa[4];
            pa[0] = ldu32(&Ps[r][kk + 2 * tig]);
            pa[1] = ldu32(&Ps[r + 8][kk + 2 * tig]);
            pa[2] = ldu32(&Ps[r][kk + 2 * tig + 8]);
            pa[3] = ldu32(&Ps[r + 8][kk + 2 * tig + 8]);
            const int l0 = kk / 2 + tig;         // keys kk+2tig, kk+2tig+1
            const int l1 = kk / 2 + tig + 4;     // keys kk+2tig+8, +9
#pragma unroll
            for (int nt = 0; nt < 16; nt++) {
                int n = nt * 8 + gid;
                unsigned b0 = ldu32(&Vs[st][l0][n * 2]);
                unsigned b1 = ldu32(&Vs[st][l1][n * 2]);
                mma_f16(o_acc[nt], pa, b0, b1);
            }
        }
    }

    // ---- epilogue: O /= l, half, plain layout ----
    __half* Og = g_O + (size_t)(b * SEQ + q0) * HID + h * HDIM;
    const float i0 = 1.f / l_run[0], i1 = 1.f / l_run[1];
#pragma unroll
    for (int nt = 0; nt < 16; nt++) {
        int c = nt * 8 + 2 * tig;
        *(__half2*)&Og[(size_t)r * HID + c] =
            __floats2half2_rn(o_acc[nt][0] * i0, o_acc[nt][1] * i0);
        *(__half2*)&Og[(size_t)(r + 8) * HID + c] =
            __floats2half2_rn(o_acc[nt][2] * i1, o_acc[nt][3] * i1);
    }
}

// ================= launch =================
extern "C" void kernel_launch(void* const* d_in, const int* in_sizes, int n_in,
                              void* d_out, int out_size)
{
    const float* X    = (const float*)d_in[0];
    const int*   mask = (const int*)  d_in[1];
    const float* Wq   = (const float*)d_in[2];
    const float* bq   = (const float*)d_in[3];
    const float* Wk   = (const float*)d_in[4];
    const float* bk   = (const float*)d_in[5];
    const float* Wv   = (const float*)d_in[6];
    const float* bv   = (const float*)d_in[7];
    const float* Wo   = (const float*)d_in[8];
    const float* bo   = (const float*)d_in[9];
    float* out = (float*)d_out;

    __half *Qp, *Kp, *Vp, *Op, *Xh, *Wqt, *Wkt, *Wvt, *Wot;
    cudaGetSymbolAddress((void**)&Qp, g_Q);
    cudaGetSymbolAddress((void**)&Kp, g_K);
    cudaGetSymbolAddress((void**)&Vp, g_V);
    cudaGetSymbolAddress((void**)&Op, g_O);
    cudaGetSymbolAddress((void**)&Xh, g_Xh);
    cudaGetSymbolAddress((void**)&Wqt, g_Wqt);
    cudaGetSymbolAddress((void**)&Wkt, g_Wkt);
    cudaGetSymbolAddress((void**)&Wvt, g_Wvt);
    cudaGetSymbolAddress((void**)&Wot, g_Wot);

    cudaFuncSetAttribute(gemm_h<0>, cudaFuncAttributeMaxDynamicSharedMemorySize, GSMEM);
    cudaFuncSetAttribute(gemm_h<1>, cudaFuncAttributeMaxDynamicSharedMemorySize, GSMEM);
    cudaFuncSetAttribute(gemm_h_kv, cudaFuncAttributeMaxDynamicSharedMemorySize, GSMEM);
    cudaFuncSetAttribute(attn_h, cudaFuncAttributeMaxDynamicSharedMemorySize, ASMEM);

    // prep: X -> half; weights -> [N][K] half
    {
        int nX8 = MROWS * HID / 8;
        h_cast<<<(nX8 + 255) / 256, 256>>>(X, Xh, nX8);
        wtrans_h<<<dim3(HID / 32, HID / 32), 256>>>(Wq, Wqt, HID, HID);
        wtrans_h<<<dim3(HID / 32, KVD / 32), 256>>>(Wk, Wkt, HID, KVD);
        wtrans_h<<<dim3(HID / 32, KVD / 32), 256>>>(Wv, Wvt, HID, KVD);
        wtrans_h<<<dim3(HID / 32, HID / 32), 256>>>(Wo, Wot, HID, HID);
    }

    dim3 blk(256);
    gemm_h<1><<<dim3(HID / 128, MROWS / 128), blk, GSMEM>>>(Xh, Wqt, bq, (void*)Qp, MROWS, HID, HID);
    gemm_h_kv<<<dim3(8, MROWS / 128), blk, GSMEM>>>(Xh, Wkt, Wvt, bk, bv, Kp, Vp, MROWS, HID);

    attn_h<<<dim3(SEQ / 64, HEADS, BATCH), dim3(128), ASMEM>>>(mask);

    gemm_h<0><<<dim3(HID / 128, MROWS / 128), blk, GSMEM>>>(Op, Wot, bo, (void*)out, MROWS, HID, HID);
}

// round 15
// speedup vs baseline: 2.1016x; 1.0132x over previous
#include <cuda_runtime.h>
#include <cuda_fp16.h>
#include <math.h>
#include <stdint.h>

#define HID     2048
#define KVD     512
#define HEADS   16
#define GROUPS  4
#define HDIM    128
#define BATCH   2
#define SEQ     2048
#define MROWS   (BATCH*SEQ)   // 4096

// ---------------- scratch (no cudaMalloc allowed) ----------------
__device__ __half g_Q[(size_t)MROWS * HID];    // half, plain [row][dim]
__device__ __half g_K[(size_t)MROWS * KVD];    // half, plain [row][dim]
__device__ __half g_V[(size_t)MROWS * KVD];    // half, key-pair interleaved
__device__ __half g_O[(size_t)MROWS * HID];    // half, plain
__device__ __half g_Xh[(size_t)MROWS * HID];   // half copy of X
__device__ __half g_Wqt[(size_t)HID * HID];    // W^T [N][K] half
__device__ __half g_Wkt[(size_t)KVD * HID];
__device__ __half g_Wvt[(size_t)KVD * HID];
__device__ __half g_Wot[(size_t)HID * HID];

// ---------------- helpers ----------------
__device__ __forceinline__ void mma_f16(float c[4], const unsigned a[4],
                                        unsigned b0, unsigned b1) {
    asm volatile(
        "mma.sync.aligned.m16n8k16.row.col.f32.f16.f16.f32 "
        "{%0,%1,%2,%3},{%4,%5,%6,%7},{%8,%9},{%0,%1,%2,%3};\n"
        : "+f"(c[0]), "+f"(c[1]), "+f"(c[2]), "+f"(c[3])
        : "r"(a[0]), "r"(a[1]), "r"(a[2]), "r"(a[3]), "r"(b0), "r"(b1));
}

__device__ __forceinline__ void cp_async16(void* smem, const void* gmem) {
    unsigned sa = (unsigned)__cvta_generic_to_shared(smem);
    asm volatile("cp.async.cg.shared.global [%0], [%1], 16;\n" :: "r"(sa), "l"(gmem));
}
#define CP_COMMIT asm volatile("cp.async.commit_group;\n")
#define CP_WAIT0  asm volatile("cp.async.wait_group 0;\n")

__device__ __forceinline__ unsigned ldu32(const __half* p) {
    return *(const unsigned*)p;
}

// ================= prep kernels =================
__global__ __launch_bounds__(256) void h_cast(const float* __restrict__ in,
                                              __half* __restrict__ out, int n8)
{
    int i = blockIdx.x * 256 + threadIdx.x;
    if (i < n8) {
        float4 v0 = ((const float4*)in)[2 * i];
        float4 v1 = ((const float4*)in)[2 * i + 1];
        __half2 o[4];
        o[0] = __floats2half2_rn(v0.x, v0.y);
        o[1] = __floats2half2_rn(v0.z, v0.w);
        o[2] = __floats2half2_rn(v1.x, v1.y);
        o[3] = __floats2half2_rn(v1.z, v1.w);
        *(uint4*)&out[8 * i] = *(uint4*)o;
    }
}

// W [K][N] fp32 -> Wt [N][K] fp16
__global__ __launch_bounds__(256) void wtrans_h(const float* __restrict__ in,
                                                __half* __restrict__ out, int K, int N)
{
    __shared__ float t[32][33];
    const int k0 = blockIdx.x * 32, n0 = blockIdx.y * 32;
    const int tx = threadIdx.x & 31, ty = threadIdx.x >> 5;
#pragma unroll
    for (int u = 0; u < 4; u++)
        t[ty + u * 8][tx] = in[(size_t)(k0 + ty + u * 8) * N + n0 + tx];
    __syncthreads();
#pragma unroll
    for (int u = 0; u < 4; u++)
        out[(size_t)(n0 + ty + u * 8) * K + k0 + tx] = __float2half(t[tx][ty + u * 8]);
}

// ================= GEMM (fp16 tensor cores): C[M,N] = A[M,K]@W[K,N] + bias ===========
// Unchanged from R14 (tensor-bound). A [M][K] half, Bt [N][K] half.
// 128x128x64 tile, 256 threads = 8 warps (4x2). Rows padded to 72 halves.
// EPI: 0 plain fp32 out; 1 half plain (Q,K); 2 half key-pair interleaved (V).
#define GBK 64
#define BKP 72
#define G_TILE (128*BKP)
#define GSMEM (4*G_TILE*2)          // 73728 B

template<int EPI>
__device__ __forceinline__ void gemm_body(
    const __half* __restrict__ A, const __half* __restrict__ Bt,
    const float* __restrict__ bias, void* Cptr,
    int M, int N, int K, int bm, int bn, __half* gsm)
{
    __half (*As)[128][BKP] = (__half(*)[128][BKP])gsm;
    __half (*Bs)[128][BKP] = (__half(*)[128][BKP])(gsm + 2 * G_TILE);

    const int tid = threadIdx.x;
    const int lane = tid & 31, wid = tid >> 5;
    const int gid = lane >> 2, tig = lane & 3;
    const int wm = wid >> 1, wn = wid & 1;

    float acc[2][8][4];
#pragma unroll
    for (int i = 0; i < 2; i++)
#pragma unroll
        for (int j = 0; j < 8; j++)
#pragma unroll
            for (int v = 0; v < 4; v++) acc[i][j][v] = 0.f;

    const int T = K / GBK;

    auto load_stage = [&](int st, int t) {
        const int k0 = t * GBK;
#pragma unroll
        for (int u = 0; u < 4; u++) {
            int id = tid + u * 256;
            int r = id >> 3, c = id & 7;
            cp_async16(&As[st][r][c * 8], A  + (size_t)(bm + r) * K + k0 + c * 8);
            cp_async16(&Bs[st][r][c * 8], Bt + (size_t)(bn + r) * K + k0 + c * 8);
        }
    };

    load_stage(0, 0);
    CP_COMMIT;

    for (int t = 0; t < T; t++) {
        const int st = t & 1;
        CP_WAIT0;
        __syncthreads();
        if (t + 1 < T) {
            load_stage(st ^ 1, t + 1);
            CP_COMMIT;
        }

#pragma unroll
        for (int kk = 0; kk < GBK; kk += 16) {
            unsigned a[2][4];
#pragma unroll
            for (int mt = 0; mt < 2; mt++) {
                int r = wm * 32 + mt * 16 + gid;
                a[mt][0] = ldu32(&As[st][r][kk + 2 * tig]);
                a[mt][1] = ldu32(&As[st][r + 8][kk + 2 * tig]);
                a[mt][2] = ldu32(&As[st][r][kk + 2 * tig + 8]);
                a[mt][3] = ldu32(&As[st][r + 8][kk + 2 * tig + 8]);
            }
#pragma unroll
            for (int nt = 0; nt < 8; nt++) {
                int c = wn * 64 + nt * 8 + gid;
                unsigned b0 = ldu32(&Bs[st][c][kk + 2 * tig]);
                unsigned b1 = ldu32(&Bs[st][c][kk + 2 * tig + 8]);
                mma_f16(acc[0][nt], a[0], b0, b1);
                mma_f16(acc[1][nt], a[1], b0, b1);
            }
        }
    }

#pragma unroll
    for (int mt = 0; mt < 2; mt++) {
        int rbase = bm + wm * 32 + mt * 16 + gid;
#pragma unroll
        for (int nt = 0; nt < 8; nt++) {
            int c = bn + wn * 64 + nt * 8 + 2 * tig;
            float bx = bias[c], by = bias[c + 1];
            float v0 = acc[mt][nt][0] + bx, v1 = acc[mt][nt][1] + by;
            float v2 = acc[mt][nt][2] + bx, v3 = acc[mt][nt][3] + by;
            if (EPI == 0) {
                float* C = (float*)Cptr;
                *(float2*)&C[(size_t)rbase * N + c] = make_float2(v0, v1);
                *(float2*)&C[(size_t)(rbase + 8) * N + c] = make_float2(v2, v3);
            } else if (EPI == 1) {
                __half* C = (__half*)Cptr;
                *(__half2*)&C[(size_t)rbase * N + c] = __floats2half2_rn(v0, v1);
                *(__half2*)&C[(size_t)(rbase + 8) * N + c] = __floats2half2_rn(v2, v3);
            } else {
                __half* C = (__half*)Cptr;
#pragma unroll
                for (int rr = 0; rr < 2; rr++) {
                    int r = rbase + rr * 8;
                    size_t base = (size_t)(r & ~1) * N + (r & 1);
                    float a0 = rr ? v2 : v0, a1 = rr ? v3 : v1;
                    C[base + (size_t)c * 2] = __float2half(a0);
                    C[base + (size_t)(c + 1) * 2] = __float2half(a1);
                }
            }
        }
    }
}

template<int EPI>
__global__ __launch_bounds__(256, 2) void gemm_h(
    const __half* __restrict__ A, const __half* __restrict__ Bt,
    const float* __restrict__ bias, void* C, int M, int N, int K)
{
    extern __shared__ __half gsm[];
    gemm_body<EPI>(A, Bt, bias, C, M, N, K,
                   blockIdx.y * 128, blockIdx.x * 128, gsm);
}

__global__ __launch_bounds__(256, 2) void gemm_h_kv(
    const __half* __restrict__ A,
    const __half* __restrict__ Wk, const __half* __restrict__ Wv,
    const float* __restrict__ bk, const float* __restrict__ bv,
    __half* __restrict__ Ck, __half* __restrict__ Cv, int M, int K)
{
    extern __shared__ __half gsm[];
    const bool isK = blockIdx.x < 4;
    const int bn = (blockIdx.x & 3) * 128;
    const int bm = blockIdx.y * 128;
    if (isK)
        gemm_body<1>(A, Wk, bk, (void*)Ck, M, KVD, K, bm, bn, gsm);
    else
        gemm_body<2>(A, Wv, bv, (void*)Cv, M, KVD, K, bm, bn, gsm);
}

// ================= Flash attention (fp16, BK=64) =================
// 128 threads = 4 warps (warp owns 16 Q rows), Q tile 64x128, K/V tiles 64 keys,
// double-buffered cp.async, 2 CTAs/SM. Softmax/barrier cost per key halved vs BK=32.
#define AQP 136                        // 68 words = 4 mod 8
#define AKP 136
#define AVL 272                        // V pair-line: 256 halves + 16 pad (136 words)
#define APP 72                         // P row: 64 keys + pad (36 words = 4 mod 8)
#define OQ_  0
#define OKs  (64*AQP)                  // 8704 halves
#define OVs  (OKs + 2*64*AKP)          // +17408
#define OPs  (OVs + 2*32*AVL)          // +17408
#define OMs  (OPs + 64*APP)            // +4608 -> 48128 halves
#define ASMEM (OMs*2 + 2*64*4)         // 96768 B -> 2 CTAs/SM

__global__ __launch_bounds__(128, 2) void attn_h(const int* __restrict__ mask)
{
    extern __shared__ __half sm[];
    __half (*Qs)[AQP]     = (__half(*)[AQP])(sm + OQ_);
    __half (*Ks)[64][AKP] = (__half(*)[64][AKP])(sm + OKs);
    __half (*Vs)[32][AVL] = (__half(*)[32][AVL])(sm + OVs);
    __half (*Ps)[APP]     = (__half(*)[APP])(sm + OPs);
    int (*Ms)[64]         = (int(*)[64])(sm + OMs);

    const int tid = threadIdx.x;
    const int w = tid >> 5, lane = tid & 31;
    const int gid = lane >> 2, tig = lane & 3;
    const int qt = blockIdx.x, h = blockIdx.y, b = blockIdx.z;
    const int g = h % GROUPS;
    const int q0 = qt * 64;

    const float scale = 0.08838834764831845f;  // 1/sqrt(128)
    const __half* Qg = g_Q + (size_t)(b * SEQ + q0) * HID + h * HDIM;
    const __half* Kg0 = g_K + (size_t)(b * SEQ) * KVD + g * HDIM;
    const __half* Vg0 = g_V + (size_t)(b * SEQ) * KVD;   // interleaved
    const int*    Mg0 = mask + b * SEQ;

    auto issue_kv = [&](int st, int kt) {
        const int k0 = kt * 64;
#pragma unroll
        for (int u = 0; u < 8; u++) {
            int id = tid + u * 128;              // 0..1023
            // K: 64 rows x 16 chunks of 8 halves
            int r = id >> 4, c = id & 15;
            cp_async16(&Ks[st][r][c * 8], Kg0 + (size_t)(k0 + r) * KVD + c * 8);
            // V: 32 pair-lines x 32 chunks; line t = keys (k0+2t, k0+2t+1)
            int line = id >> 5, cc = id & 31;
            const __half* src = Vg0 + (size_t)(k0 + 2 * line) * KVD + g * 256 + cc * 8;
            cp_async16(&Vs[st][line][cc * 8], src);
        }
        if (tid < 16) cp_async16(&Ms[st][tid * 4], Mg0 + k0 + tid * 4);
    };

    issue_kv(0, 0);
    CP_COMMIT;

    // Q prologue: load half, scale in fp32, re-round to half
#pragma unroll
    for (int u = 0; u < 8; u++) {
        int idx = tid + u * 128;
        int r = idx >> 4, c8 = idx & 15;
        uint4 raw = *(const uint4*)(Qg + (size_t)r * HID + c8 * 8);
        __half2* hp = (__half2*)&raw;
        __half2 o[4];
#pragma unroll
        for (int j = 0; j < 4; j++) {
            float2 f = __half22float2(hp[j]);
            o[j] = __floats2half2_rn(f.x * scale, f.y * scale);
        }
        *(uint4*)&Qs[r][c8 * 8] = *(uint4*)o;
    }

    float m_run[2] = {-1e30f, -1e30f};
    float l_run[2] = {0.f, 0.f};
    float o_acc[16][4];
#pragma unroll
    for (int nt = 0; nt < 16; nt++)
#pragma unroll
        for (int v = 0; v < 4; v++) o_acc[nt][v] = 0.f;

    const int r = w * 16 + gid;

    for (int kt = 0; kt < SEQ / 64; kt++) {
        const int st = kt & 1;
        CP_WAIT0;
        __syncthreads();
        if (kt + 1 < SEQ / 64) {
            issue_kv(st ^ 1, kt + 1);
            CP_COMMIT;
        }

        // ---- S = Q @ K^T (16 rows x 64 keys per warp) ----
        float s[8][4];
#pragma unroll
        for (int nt = 0; nt < 8; nt++)
#pragma unroll
            for (int v = 0; v < 4; v++) s[nt][v] = 0.f;

#pragma unroll
        for (int ks = 0; ks < 8; ks++) {
            const int kk = ks * 16;
            unsigned qa[4];
            qa[0] = ldu32(&Qs[r][kk + 2 * tig]);
            qa[1] = ldu32(&Qs[r + 8][kk + 2 * tig]);
            qa[2] = ldu32(&Qs[r][kk + 2 * tig + 8]);
            qa[3] = ldu32(&Qs[r + 8][kk + 2 * tig + 8]);
#pragma unroll
            for (int nt = 0; nt < 8; nt++) {
                int key = nt * 8 + gid;
                unsigned b0 = ldu32(&Ks[st][key][kk + 2 * tig]);
                unsigned b1 = ldu32(&Ks[st][key][kk + 2 * tig + 8]);
                mma_f16(s[nt], qa, b0, b1);
            }
        }

        // ---- mask ----
#pragma unroll
        for (int nt = 0; nt < 8; nt++) {
            int c = nt * 8 + 2 * tig;
            if (Ms[st][c] == 0)     { s[nt][0] = -1e30f; s[nt][2] = -1e30f; }
            if (Ms[st][c + 1] == 0) { s[nt][1] = -1e30f; s[nt][3] = -1e30f; }
        }

        // ---- online softmax (row halves gid, gid+8), once per 64 keys ----
#pragma unroll
        for (int hh = 0; hh < 2; hh++) {
            float mx = -1e30f;
#pragma unroll
            for (int nt = 0; nt < 8; nt++)
                mx = fmaxf(mx, fmaxf(s[nt][2 * hh], s[nt][2 * hh + 1]));
            mx = fmaxf(mx, __shfl_xor_sync(0xffffffffu, mx, 1));
            mx = fmaxf(mx, __shfl_xor_sync(0xffffffffu, mx, 2));
            float mnew = fmaxf(m_run[hh], mx);
            float corr = __expf(m_run[hh] - mnew);
            float sum = 0.f;
#pragma unroll
            for (int nt = 0; nt < 8; nt++) {
                float p0 = __expf(s[nt][2 * hh] - mnew);
                float p1 = __expf(s[nt][2 * hh + 1] - mnew);
                s[nt][2 * hh] = p0; s[nt][2 * hh + 1] = p1;
                sum += p0 + p1;
            }
            sum += __shfl_xor_sync(0xffffffffu, sum, 1);
            sum += __shfl_xor_sync(0xffffffffu, sum, 2);
            l_run[hh] = l_run[hh] * corr + sum;
            if (mnew > m_run[hh]) {
                m_run[hh] = mnew;
#pragma unroll
                for (int nt = 0; nt < 16; nt++) {
                    o_acc[nt][2 * hh] *= corr;
                    o_acc[nt][2 * hh + 1] *= corr;
                }
            }
        }

        // ---- store P as half2 (natural key order) ----
#pragma unroll
        for (int nt = 0; nt < 8; nt++) {
            int c = nt * 8 + 2 * tig;
            *(__half2*)&Ps[r][c]     = __floats2half2_rn(s[nt][0], s[nt][1]);
            *(__half2*)&Ps[r + 8][c] = __floats2half2_rn(s[nt][2], s[nt][3]);
        }
        __syncwarp();

        // ---- O += P @ V (V key-pair interleaved) ----
#pragma unroll
        for (int ks = 0; ks < 4; ks++) {
            const int kk = ks * 16;
            unsigned pa[4];
            pa[0] = ldu32(&Ps[r][kk + 2 * tig]);
            pa[1] = ldu32(&Ps[r + 8][kk + 2 * tig]);
            pa[2] = ldu32(&Ps[r][kk + 2 * tig + 8]);
            pa[3] = ldu32(&Ps[r + 8][kk + 2 * tig + 8]);
            const int l0 = kk / 2 + tig;         // keys kk+2tig, kk+2tig+1
            const int l1 = kk / 2 + tig + 4;     // keys kk+8+2tig, +1
#pragma unroll
            for (int nt = 0; nt < 16; nt++) {
                int n = nt * 8 + gid;
                unsigned b0 = ldu32(&Vs[st][l0][n * 2]);
                unsigned b1 = ldu32(&Vs[st][l1][n * 2]);
                mma_f16(o_acc[nt], pa, b0, b1);
            }
        }
    }

    // ---- epilogue: O /= l, half, plain layout ----
    __half* Og = g_O + (size_t)(b * SEQ + q0) * HID + h * HDIM;
    const float i0 = 1.f / l_run[0], i1 = 1.f / l_run[1];
#pragma unroll
    for (int nt = 0; nt < 16; nt++) {
        int c = nt * 8 + 2 * tig;
        *(__half2*)&Og[(size_t)r * HID + c] =
            __floats2half2_rn(o_acc[nt][0] * i0, o_acc[nt][1] * i0);
        *(__half2*)&Og[(size_t)(r + 8) * HID + c] =
            __floats2half2_rn(o_acc[nt][2] * i1, o_acc[nt][3] * i1);
    }
}

// ================= launch =================
extern "C" void kernel_launch(void* const* d_in, const int* in_sizes, int n_in,
                              void* d_out, int out_size)
{
    const float* X    = (const float*)d_in[0];
    const int*   mask = (const int*)  d_in[1];
    const float* Wq   = (const float*)d_in[2];
    const float* bq   = (const float*)d_in[3];
    const float* Wk   = (const float*)d_in[4];
    const float* bk   = (const float*)d_in[5];
    const float* Wv   = (const float*)d_in[6];
    const float* bv   = (const float*)d_in[7];
    const float* Wo   = (const float*)d_in[8];
    const float* bo   = (const float*)d_in[9];
    float* out = (float*)d_out;

    __half *Qp, *Kp, *Vp, *Op, *Xh, *Wqt, *Wkt, *Wvt, *Wot;
    cudaGetSymbolAddress((void**)&Qp, g_Q);
    cudaGetSymbolAddress((void**)&Kp, g_K);
    cudaGetSymbolAddress((void**)&Vp, g_V);
    cudaGetSymbolAddress((void**)&Op, g_O);
    cudaGetSymbolAddress((void**)&Xh, g_Xh);
    cudaGetSymbolAddress((void**)&Wqt, g_Wqt);
    cudaGetSymbolAddress((void**)&Wkt, g_Wkt);
    cudaGetSymbolAddress((void**)&Wvt, g_Wvt);
    cudaGetSymbolAddress((void**)&Wot, g_Wot);

    cudaFuncSetAttribute(gemm_h<0>, cudaFuncAttributeMaxDynamicSharedMemorySize, GSMEM);
    cudaFuncSetAttribute(gemm_h<1>, cudaFuncAttributeMaxDynamicSharedMemorySize, GSMEM);
    cudaFuncSetAttribute(gemm_h_kv, cudaFuncAttributeMaxDynamicSharedMemorySize, GSMEM);
    cudaFuncSetAttribute(attn_h, cudaFuncAttributeMaxDynamicSharedMemorySize, ASMEM);

    // prep: X -> half; weights -> [N][K] half
    {
        int nX8 = MROWS * HID / 8;
        h_cast<<<(nX8 + 255) / 256, 256>>>(X, Xh, nX8);
        wtrans_h<<<dim3(HID / 32, HID / 32), 256>>>(Wq, Wqt, HID, HID);
        wtrans_h<<<dim3(HID / 32, KVD / 32), 256>>>(Wk, Wkt, HID, KVD);
        wtrans_h<<<dim3(HID / 32, KVD / 32), 256>>>(Wv, Wvt, HID, KVD);
        wtrans_h<<<dim3(HID / 32, HID / 32), 256>>>(Wo, Wot, HID, HID);
    }

    dim3 blk(256);
    gemm_h<1><<<dim3(HID / 128, MROWS / 128), blk, GSMEM>>>(Xh, Wqt, bq, (void*)Qp, MROWS, HID, HID);
    gemm_h_kv<<<dim3(8, MROWS / 128), blk, GSMEM>>>(Xh, Wkt, Wvt, bk, bv, Kp, Vp, MROWS, HID);

    attn_h<<<dim3(SEQ / 64, HEADS, BATCH), dim3(128), ASMEM>>>(mask);

    gemm_h<0><<<dim3(HID / 128, MROWS / 128), blk, GSMEM>>>(Op, Wot, bo, (void*)out, MROWS, HID, HID);
}

// round 16
// speedup vs baseline: 2.1979x; 1.0458x over previous
#include <cuda_runtime.h>
#include <cuda_fp16.h>
#include <math.h>
#include <stdint.h>

#define HID     2048
#define KVD     512
#define HEADS   16
#define GROUPS  4
#define HDIM    128
#define BATCH   2
#define SEQ     2048
#define MROWS   (BATCH*SEQ)   // 4096

// ---------------- scratch (no cudaMalloc allowed) ----------------
__device__ __half g_Q[(size_t)MROWS * HID];    // half, plain [row][dim]
__device__ __half g_K[(size_t)MROWS * KVD];    // half, plain [row][dim]
__device__ __half g_V[(size_t)MROWS * KVD];    // half, key-pair interleaved
__device__ __half g_O[(size_t)MROWS * HID];    // half, plain
__device__ __half g_Xh[(size_t)MROWS * HID];   // half copy of X
__device__ __half g_Wqt[(size_t)HID * HID];    // W^T [N][K] half
__device__ __half g_Wkt[(size_t)KVD * HID];
__device__ __half g_Wvt[(size_t)KVD * HID];
__device__ __half g_Wot[(size_t)HID * HID];

// ---------------- helpers ----------------
__device__ __forceinline__ void mma_f16(float c[4], const unsigned a[4],
                                        unsigned b0, unsigned b1) {
    asm volatile(
        "mma.sync.aligned.m16n8k16.row.col.f32.f16.f16.f32 "
        "{%0,%1,%2,%3},{%4,%5,%6,%7},{%8,%9},{%0,%1,%2,%3};\n"
        : "+f"(c[0]), "+f"(c[1]), "+f"(c[2]), "+f"(c[3])
        : "r"(a[0]), "r"(a[1]), "r"(a[2]), "r"(a[3]), "r"(b0), "r"(b1));
}

__device__ __forceinline__ void cp_async16(void* smem, const void* gmem) {
    unsigned sa = (unsigned)__cvta_generic_to_shared(smem);
    asm volatile("cp.async.cg.shared.global [%0], [%1], 16;\n" :: "r"(sa), "l"(gmem));
}
#define CP_COMMIT asm volatile("cp.async.commit_group;\n")
#define CP_WAIT0  asm volatile("cp.async.wait_group 0;\n")

__device__ __forceinline__ unsigned ldu32(const __half* p) {
    return *(const unsigned*)p;
}
__device__ __forceinline__ unsigned packh2(float a, float b) {
    __half2 h = __floats2half2_rn(a, b);
    return *(unsigned*)&h;
}

// ================= fused prep kernel =================
// blocks [0,4096): X fp32->fp16 cast (8 elems/thread)
// blocks [4096,+4096): Wq transpose; [+1024): Wk; [+1024): Wv; [+4096): Wo
__global__ __launch_bounds__(256) void prep_all(
    const float* __restrict__ X,
    const float* __restrict__ Wq, const float* __restrict__ Wk,
    const float* __restrict__ Wv, const float* __restrict__ Wo,
    __half* __restrict__ Xh,
    __half* __restrict__ Wqt, __half* __restrict__ Wkt,
    __half* __restrict__ Wvt, __half* __restrict__ Wot)
{
    int b = blockIdx.x;
    if (b < 4096) {
        int i = b * 256 + threadIdx.x;      // < 1048576 = MROWS*HID/8
        float4 v0 = ((const float4*)X)[2 * i];
        float4 v1 = ((const float4*)X)[2 * i + 1];
        __half2 o[4];
        o[0] = __floats2half2_rn(v0.x, v0.y);
        o[1] = __floats2half2_rn(v0.z, v0.w);
        o[2] = __floats2half2_rn(v1.x, v1.y);
        o[3] = __floats2half2_rn(v1.z, v1.w);
        *(uint4*)&g_Xh[8 * i] = *(uint4*)o;
        return;
    }
    b -= 4096;
    const float* in; __half* out; int N;
    if (b < 4096)        { in = Wq; out = Wqt; N = HID; }
    else if (b < 5120)   { in = Wk; out = Wkt; N = KVD; b -= 4096; }
    else if (b < 6144)   { in = Wv; out = Wvt; N = KVD; b -= 5120; }
    else                 { in = Wo; out = Wot; N = HID; b -= 6144; }

    __shared__ float t[32][33];
    const int k0 = (b & 63) * 32, n0 = (b >> 6) * 32;   // K = 2048 always
    const int tx = threadIdx.x & 31, ty = threadIdx.x >> 5;
#pragma unroll
    for (int u = 0; u < 4; u++)
        t[ty + u * 8][tx] = in[(size_t)(k0 + ty + u * 8) * N + n0 + tx];
    __syncthreads();
#pragma unroll
    for (int u = 0; u < 4; u++)
        out[(size_t)(n0 + ty + u * 8) * HID + k0 + tx] = __float2half(t[tx][ty + u * 8]);
}

// ================= GEMM (fp16 tensor cores): C[M,N] = A[M,K]@W[K,N] + bias ===========
// Unchanged from R14/R15 (tensor-bound). A [M][K] half, Bt [N][K] half.
#define GBK 64
#define BKP 72
#define G_TILE (128*BKP)
#define GSMEM (4*G_TILE*2)          // 73728 B

template<int EPI>
__device__ __forceinline__ void gemm_body(
    const __half* __restrict__ A, const __half* __restrict__ Bt,
    const float* __restrict__ bias, void* Cptr,
    int M, int N, int K, int bm, int bn, __half* gsm)
{
    __half (*As)[128][BKP] = (__half(*)[128][BKP])gsm;
    __half (*Bs)[128][BKP] = (__half(*)[128][BKP])(gsm + 2 * G_TILE);

    const int tid = threadIdx.x;
    const int lane = tid & 31, wid = tid >> 5;
    const int gid = lane >> 2, tig = lane & 3;
    const int wm = wid >> 1, wn = wid & 1;

    float acc[2][8][4];
#pragma unroll
    for (int i = 0; i < 2; i++)
#pragma unroll
        for (int j = 0; j < 8; j++)
#pragma unroll
            for (int v = 0; v < 4; v++) acc[i][j][v] = 0.f;

    const int T = K / GBK;

    auto load_stage = [&](int st, int t) {
        const int k0 = t * GBK;
#pragma unroll
        for (int u = 0; u < 4; u++) {
            int id = tid + u * 256;
            int r = id >> 3, c = id & 7;
            cp_async16(&As[st][r][c * 8], A  + (size_t)(bm + r) * K + k0 + c * 8);
            cp_async16(&Bs[st][r][c * 8], Bt + (size_t)(bn + r) * K + k0 + c * 8);
        }
    };

    load_stage(0, 0);
    CP_COMMIT;

    for (int t = 0; t < T; t++) {
        const int st = t & 1;
        CP_WAIT0;
        __syncthreads();
        if (t + 1 < T) {
            load_stage(st ^ 1, t + 1);
            CP_COMMIT;
        }

#pragma unroll
        for (int kk = 0; kk < GBK; kk += 16) {
            unsigned a[2][4];
#pragma unroll
            for (int mt = 0; mt < 2; mt++) {
                int r = wm * 32 + mt * 16 + gid;
                a[mt][0] = ldu32(&As[st][r][kk + 2 * tig]);
                a[mt][1] = ldu32(&As[st][r + 8][kk + 2 * tig]);
                a[mt][2] = ldu32(&As[st][r][kk + 2 * tig + 8]);
                a[mt][3] = ldu32(&As[st][r + 8][kk + 2 * tig + 8]);
            }
#pragma unroll
            for (int nt = 0; nt < 8; nt++) {
                int c = wn * 64 + nt * 8 + gid;
                unsigned b0 = ldu32(&Bs[st][c][kk + 2 * tig]);
                unsigned b1 = ldu32(&Bs[st][c][kk + 2 * tig + 8]);
                mma_f16(acc[0][nt], a[0], b0, b1);
                mma_f16(acc[1][nt], a[1], b0, b1);
            }
        }
    }

#pragma unroll
    for (int mt = 0; mt < 2; mt++) {
        int rbase = bm + wm * 32 + mt * 16 + gid;
#pragma unroll
        for (int nt = 0; nt < 8; nt++) {
            int c = bn + wn * 64 + nt * 8 + 2 * tig;
            float bx = bias[c], by = bias[c + 1];
            float v0 = acc[mt][nt][0] + bx, v1 = acc[mt][nt][1] + by;
            float v2 = acc[mt][nt][2] + bx, v3 = acc[mt][nt][3] + by;
            if (EPI == 0) {
                float* C = (float*)Cptr;
                *(float2*)&C[(size_t)rbase * N + c] = make_float2(v0, v1);
                *(float2*)&C[(size_t)(rbase + 8) * N + c] = make_float2(v2, v3);
            } else if (EPI == 1) {
                __half* C = (__half*)Cptr;
                *(__half2*)&C[(size_t)rbase * N + c] = __floats2half2_rn(v0, v1);
                *(__half2*)&C[(size_t)(rbase + 8) * N + c] = __floats2half2_rn(v2, v3);
            } else {
                __half* C = (__half*)Cptr;
#pragma unroll
                for (int rr = 0; rr < 2; rr++) {
                    int r = rbase + rr * 8;
                    size_t base = (size_t)(r & ~1) * N + (r & 1);
                    float a0 = rr ? v2 : v0, a1 = rr ? v3 : v1;
                    C[base + (size_t)c * 2] = __float2half(a0);
                    C[base + (size_t)(c + 1) * 2] = __float2half(a1);
                }
            }
        }
    }
}

template<int EPI>
__global__ __launch_bounds__(256, 2) void gemm_h(
    const __half* __restrict__ A, const __half* __restrict__ Bt,
    const float* __restrict__ bias, void* C, int M, int N, int K)
{
    extern __shared__ __half gsm[];
    gemm_body<EPI>(A, Bt, bias, C, M, N, K,
                   blockIdx.y * 128, blockIdx.x * 128, gsm);
}

__global__ __launch_bounds__(256, 2) void gemm_h_kv(
    const __half* __restrict__ A,
    const __half* __restrict__ Wk, const __half* __restrict__ Wv,
    const float* __restrict__ bk, const float* __restrict__ bv,
    __half* __restrict__ Ck, __half* __restrict__ Cv, int M, int K)
{
    extern __shared__ __half gsm[];
    const bool isK = blockIdx.x < 4;
    const int bn = (blockIdx.x & 3) * 128;
    const int bm = blockIdx.y * 128;
    if (isK)
        gemm_body<1>(A, Wk, bk, (void*)Ck, M, KVD, K, bm, bn, gsm);
    else
        gemm_body<2>(A, Wv, bv, (void*)Cv, M, KVD, K, bm, bn, gsm);
}

// ================= Flash attention (fp16, BK=64, register-resident Q & P) ==========
// 128 threads = 4 warps (warp owns 16 Q rows), Q tile 64x128, K/V tiles 64 keys.
// Q fragments hoisted to registers once; P never touches smem (S C-frag layout
// == P A-frag layout when packed as half2).
#define AQP 136                        // 68 words = 4 mod 8
#define AKP 136
#define AVL 272                        // V pair-line: 256 halves + 16 pad
#define OQ_  0
#define OKs  (64*AQP)                  // 8704 halves
#define OVs  (OKs + 2*64*AKP)          // +17408
#define OMs  (OVs + 2*32*AVL)          // +17408 -> 43520 halves
#define ASMEM (OMs*2 + 2*64*4)         // 87552 B -> 2 CTAs/SM

__global__ __launch_bounds__(128, 2) void attn_h(const int* __restrict__ mask)
{
    extern __shared__ __half sm[];
    __half (*Qs)[AQP]     = (__half(*)[AQP])(sm + OQ_);
    __half (*Ks)[64][AKP] = (__half(*)[64][AKP])(sm + OKs);
    __half (*Vs)[32][AVL] = (__half(*)[32][AVL])(sm + OVs);
    int (*Ms)[64]         = (int(*)[64])(sm + OMs);

    const int tid = threadIdx.x;
    const int w = tid >> 5, lane = tid & 31;
    const int gid = lane >> 2, tig = lane & 3;
    const int qt = blockIdx.x, h = blockIdx.y, b = blockIdx.z;
    const int g = h % GROUPS;
    const int q0 = qt * 64;

    const float scale = 0.08838834764831845f;  // 1/sqrt(128)
    const __half* Qg = g_Q + (size_t)(b * SEQ + q0) * HID + h * HDIM;
    const __half* Kg0 = g_K + (size_t)(b * SEQ) * KVD + g * HDIM;
    const __half* Vg0 = g_V + (size_t)(b * SEQ) * KVD;   // interleaved
    const int*    Mg0 = mask + b * SEQ;

    auto issue_kv = [&](int st, int kt) {
        const int k0 = kt * 64;
#pragma unroll
        for (int u = 0; u < 8; u++) {
            int id = tid + u * 128;
            int r = id >> 4, c = id & 15;
            cp_async16(&Ks[st][r][c * 8], Kg0 + (size_t)(k0 + r) * KVD + c * 8);
            int line = id >> 5, cc = id & 31;
            const __half* src = Vg0 + (size_t)(k0 + 2 * line) * KVD + g * 256 + cc * 8;
            cp_async16(&Vs[st][line][cc * 8], src);
        }
        if (tid < 16) cp_async16(&Ms[st][tid * 4], Mg0 + k0 + tid * 4);
    };

    issue_kv(0, 0);
    CP_COMMIT;

    // Q prologue: load half, scale in fp32, re-round to half, stage in smem
#pragma unroll
    for (int u = 0; u < 8; u++) {
        int idx = tid + u * 128;
        int r = idx >> 4, c8 = idx & 15;
        uint4 raw = *(const uint4*)(Qg + (size_t)r * HID + c8 * 8);
        __half2* hp = (__half2*)&raw;
        __half2 o[4];
#pragma unroll
        for (int j = 0; j < 4; j++) {
            float2 f = __half22float2(hp[j]);
            o[j] = __floats2half2_rn(f.x * scale, f.y * scale);
        }
        *(uint4*)&Qs[r][c8 * 8] = *(uint4*)o;
    }
    __syncthreads();   // Qs visible across warps

    // hoist Q fragments to registers (read once, reuse every kt iteration)
    const int r = w * 16 + gid;
    unsigned qa[8][4];
#pragma unroll
    for (int ks = 0; ks < 8; ks++) {
        const int kk = ks * 16;
        qa[ks][0] = ldu32(&Qs[r][kk + 2 * tig]);
        qa[ks][1] = ldu32(&Qs[r + 8][kk + 2 * tig]);
        qa[ks][2] = ldu32(&Qs[r][kk + 2 * tig + 8]);
        qa[ks][3] = ldu32(&Qs[r + 8][kk + 2 * tig + 8]);
    }

    float m_run[2] = {-1e30f, -1e30f};
    float l_run[2] = {0.f, 0.f};
    float o_acc[16][4];
#pragma unroll
    for (int nt = 0; nt < 16; nt++)
#pragma unroll
        for (int v = 0; v < 4; v++) o_acc[nt][v] = 0.f;

    for (int kt = 0; kt < SEQ / 64; kt++) {
        const int st = kt & 1;
        CP_WAIT0;
        __syncthreads();
        if (kt + 1 < SEQ / 64) {
            issue_kv(st ^ 1, kt + 1);
            CP_COMMIT;
        }

        // ---- S = Q @ K^T (16 rows x 64 keys per warp) ----
        float s[8][4];
#pragma unroll
        for (int nt = 0; nt < 8; nt++)
#pragma unroll
            for (int v = 0; v < 4; v++) s[nt][v] = 0.f;

#pragma unroll
        for (int ks = 0; ks < 8; ks++) {
            const int kk = ks * 16;
#pragma unroll
            for (int nt = 0; nt < 8; nt++) {
                int key = nt * 8 + gid;
                unsigned b0 = ldu32(&Ks[st][key][kk + 2 * tig]);
                unsigned b1 = ldu32(&Ks[st][key][kk + 2 * tig + 8]);
                mma_f16(s[nt], qa[ks], b0, b1);
            }
        }

        // ---- mask ----
#pragma unroll
        for (int nt = 0; nt < 8; nt++) {
            int c = nt * 8 + 2 * tig;
            if (Ms[st][c] == 0)     { s[nt][0] = -1e30f; s[nt][2] = -1e30f; }
            if (Ms[st][c + 1] == 0) { s[nt][1] = -1e30f; s[nt][3] = -1e30f; }
        }

        // ---- online softmax (row halves gid, gid+8) ----
#pragma unroll
        for (int hh = 0; hh < 2; hh++) {
            float mx = -1e30f;
#pragma unroll
            for (int nt = 0; nt < 8; nt++)
                mx = fmaxf(mx, fmaxf(s[nt][2 * hh], s[nt][2 * hh + 1]));
            mx = fmaxf(mx, __shfl_xor_sync(0xffffffffu, mx, 1));
            mx = fmaxf(mx, __shfl_xor_sync(0xffffffffu, mx, 2));
            float mnew = fmaxf(m_run[hh], mx);
            float corr = __expf(m_run[hh] - mnew);
            float sum = 0.f;
#pragma unroll
            for (int nt = 0; nt < 8; nt++) {
                float p0 = __expf(s[nt][2 * hh] - mnew);
                float p1 = __expf(s[nt][2 * hh + 1] - mnew);
                s[nt][2 * hh] = p0; s[nt][2 * hh + 1] = p1;
                sum += p0 + p1;
            }
            sum += __shfl_xor_sync(0xffffffffu, sum, 1);
            sum += __shfl_xor_sync(0xffffffffu, sum, 2);
            l_run[hh] = l_run[hh] * corr + sum;
            if (mnew > m_run[hh]) {
                m_run[hh] = mnew;
#pragma unroll
                for (int nt = 0; nt < 16; nt++) {
                    o_acc[nt][2 * hh] *= corr;
                    o_acc[nt][2 * hh + 1] *= corr;
                }
            }
        }

        // ---- O += P @ V : P taken directly from S registers (C-frag == A-frag) ----
#pragma unroll
        for (int ks = 0; ks < 4; ks++) {
            const int kk = ks * 16;
            unsigned pa[4];
            pa[0] = packh2(s[2 * ks][0], s[2 * ks][1]);          // row g,   keys kk+2tig..+1
            pa[1] = packh2(s[2 * ks][2], s[2 * ks][3]);          // row g+8
            pa[2] = packh2(s[2 * ks + 1][0], s[2 * ks + 1][1]);  // row g,   keys kk+8+2tig..+1
            pa[3] = packh2(s[2 * ks + 1][2], s[2 * ks + 1][3]);  // row g+8
            const int l0 = kk / 2 + tig;         // keys kk+2tig, kk+2tig+1
            const int l1 = kk / 2 + tig + 4;     // keys kk+8+2tig, +1
#pragma unroll
            for (int nt = 0; nt < 16; nt++) {
                int n = nt * 8 + gid;
                unsigned b0 = ldu32(&Vs[st][l0][n * 2]);
                unsigned b1 = ldu32(&Vs[st][l1][n * 2]);
                mma_f16(o_acc[nt], pa, b0, b1);
            }
        }
    }

    // ---- epilogue: O /= l, half, plain layout ----
    __half* Og = g_O + (size_t)(b * SEQ + q0) * HID + h * HDIM;
    const float i0 = 1.f / l_run[0], i1 = 1.f / l_run[1];
#pragma unroll
    for (int nt = 0; nt < 16; nt++) {
        int c = nt * 8 + 2 * tig;
        *(__half2*)&Og[(size_t)r * HID + c] =
            __floats2half2_rn(o_acc[nt][0] * i0, o_acc[nt][1] * i0);
        *(__half2*)&Og[(size_t)(r + 8) * HID + c] =
            __floats2half2_rn(o_acc[nt][2] * i1, o_acc[nt][3] * i1);
    }
}

// ================= launch =================
extern "C" void kernel_launch(void* const* d_in, const int* in_sizes, int n_in,
                              void* d_out, int out_size)
{
    const float* X    = (const float*)d_in[0];
    const int*   mask = (const int*)  d_in[1];
    const float* Wq   = (const float*)d_in[2];
    const float* bq   = (const float*)d_in[3];
    const float* Wk   = (const float*)d_in[4];
    const float* bk   = (const float*)d_in[5];
    const float* Wv   = (const float*)d_in[6];
    const float* bv   = (const float*)d_in[7];
    const float* Wo   = (const float*)d_in[8];
    const float* bo   = (const float*)d_in[9];
    float* out = (float*)d_out;

    __half *Qp, *Kp, *Vp, *Op, *Xh, *Wqt, *Wkt, *Wvt, *Wot;
    cudaGetSymbolAddress((void**)&Qp, g_Q);
    cudaGetSymbolAddress((void**)&Kp, g_K);
    cudaGetSymbolAddress((void**)&Vp, g_V);
    cudaGetSymbolAddress((void**)&Op, g_O);
    cudaGetSymbolAddress((void**)&Xh, g_Xh);
    cudaGetSymbolAddress((void**)&Wqt, g_Wqt);
    cudaGetSymbolAddress((void**)&Wkt, g_Wkt);
    cudaGetSymbolAddress((void**)&Wvt, g_Wvt);
    cudaGetSymbolAddress((void**)&Wot, g_Wot);

    cudaFuncSetAttribute(gemm_h<0>, cudaFuncAttributeMaxDynamicSharedMemorySize, GSMEM);
    cudaFuncSetAttribute(gemm_h<1>, cudaFuncAttributeMaxDynamicSharedMemorySize, GSMEM);
    cudaFuncSetAttribute(gemm_h_kv, cudaFuncAttributeMaxDynamicSharedMemorySize, GSMEM);
    cudaFuncSetAttribute(attn_h, cudaFuncAttributeMaxDynamicSharedMemorySize, ASMEM);

    // fused prep: X cast + 4 weight transposes in one launch
    prep_all<<<14336, 256>>>(X, Wq, Wk, Wv, Wo, Xh, Wqt, Wkt, Wvt, Wot);

    dim3 blk(256);
    gemm_h<1><<<dim3(HID / 128, MROWS / 128), blk, GSMEM>>>(Xh, Wqt, bq, (void*)Qp, MROWS, HID, HID);
    gemm_h_kv<<<dim3(8, MROWS / 128), blk, GSMEM>>>(Xh, Wkt, Wvt, bk, bv, Kp, Vp, MROWS, HID);

    attn_h<<<dim3(SEQ / 64, HEADS, BATCH), dim3(128), ASMEM>>>(mask);

    gemm_h<0><<<dim3(HID / 128, MROWS / 128), blk, GSMEM>>>(Op, Wot, bo, (void*)out, MROWS, HID, HID);
}

// round 17
// speedup vs baseline: 2.2231x; 1.0115x over previous
#include <cuda_runtime.h>
#include <cuda_fp16.h>
#include <math.h>
#include <stdint.h>

#define HID     2048
#define KVD     512
#define HEADS   16
#define GROUPS  4
#define HDIM    128
#define BATCH   2
#define SEQ     2048
#define MROWS   (BATCH*SEQ)   // 4096

// ---------------- scratch (no cudaMalloc allowed) ----------------
__device__ __half g_Q[(size_t)MROWS * HID];    // half, plain [row][dim]
__device__ __half g_K[(size_t)MROWS * KVD];    // half, plain [row][dim]
__device__ __half g_V[(size_t)MROWS * KVD];    // half, key-pair interleaved
__device__ __half g_O[(size_t)MROWS * HID];    // half, plain
__device__ __half g_Xh[(size_t)MROWS * HID];   // half copy of X
__device__ __half g_Wqt[(size_t)HID * HID];    // W^T [N][K] half
__device__ __half g_Wkt[(size_t)KVD * HID];
__device__ __half g_Wvt[(size_t)KVD * HID];
__device__ __half g_Wot[(size_t)HID * HID];

// ---------------- helpers ----------------
__device__ __forceinline__ void mma_f16(float c[4], const unsigned a[4],
                                        unsigned b0, unsigned b1) {
    asm volatile(
        "mma.sync.aligned.m16n8k16.row.col.f32.f16.f16.f32 "
        "{%0,%1,%2,%3},{%4,%5,%6,%7},{%8,%9},{%0,%1,%2,%3};\n"
        : "+f"(c[0]), "+f"(c[1]), "+f"(c[2]), "+f"(c[3])
        : "r"(a[0]), "r"(a[1]), "r"(a[2]), "r"(a[3]), "r"(b0), "r"(b1));
}

__device__ __forceinline__ void cp_async16(void* smem, const void* gmem) {
    unsigned sa = (unsigned)__cvta_generic_to_shared(smem);
    asm volatile("cp.async.cg.shared.global [%0], [%1], 16;\n" :: "r"(sa), "l"(gmem));
}
#define CP_COMMIT asm volatile("cp.async.commit_group;\n")
#define CP_WAIT0  asm volatile("cp.async.wait_group 0;\n")

__device__ __forceinline__ unsigned ldu32(const __half* p) {
    return *(const unsigned*)p;
}
__device__ __forceinline__ unsigned packh2(float a, float b) {
    __half2 h = __floats2half2_rn(a, b);
    return *(unsigned*)&h;
}

// ================= fused prep kernel =================
// blocks [0,4096): X fp32->fp16 cast (8 elems/thread)
// blocks [4096,+4096): Wq transpose; [+1024): Wk; [+1024): Wv; [+4096): Wo
__global__ __launch_bounds__(256) void prep_all(
    const float* __restrict__ X,
    const float* __restrict__ Wq, const float* __restrict__ Wk,
    const float* __restrict__ Wv, const float* __restrict__ Wo,
    __half* __restrict__ Xh,
    __half* __restrict__ Wqt, __half* __restrict__ Wkt,
    __half* __restrict__ Wvt, __half* __restrict__ Wot)
{
    int b = blockIdx.x;
    if (b < 4096) {
        int i = b * 256 + threadIdx.x;
        float4 v0 = ((const float4*)X)[2 * i];
        float4 v1 = ((const float4*)X)[2 * i + 1];
        __half2 o[4];
        o[0] = __floats2half2_rn(v0.x, v0.y);
        o[1] = __floats2half2_rn(v0.z, v0.w);
        o[2] = __floats2half2_rn(v1.x, v1.y);
        o[3] = __floats2half2_rn(v1.z, v1.w);
        *(uint4*)&g_Xh[8 * i] = *(uint4*)o;
        return;
    }
    b -= 4096;
    const float* in; __half* out; int N;
    if (b < 4096)        { in = Wq; out = Wqt; N = HID; }
    else if (b < 5120)   { in = Wk; out = Wkt; N = KVD; b -= 4096; }
    else if (b < 6144)   { in = Wv; out = Wvt; N = KVD; b -= 5120; }
    else                 { in = Wo; out = Wot; N = HID; b -= 6144; }

    __shared__ float t[32][33];
    const int k0 = (b & 63) * 32, n0 = (b >> 6) * 32;   // K = 2048 always
    const int tx = threadIdx.x & 31, ty = threadIdx.x >> 5;
#pragma unroll
    for (int u = 0; u < 4; u++)
        t[ty + u * 8][tx] = in[(size_t)(k0 + ty + u * 8) * N + n0 + tx];
    __syncthreads();
#pragma unroll
    for (int u = 0; u < 4; u++)
        out[(size_t)(n0 + ty + u * 8) * HID + k0 + tx] = __float2half(t[tx][ty + u * 8]);
}

// ================= GEMM (fp16 tensor cores): C[M,N] = A[M,K]@W[K,N] + bias ===========
// A [M][K] half, Bt [N][K] half. 128x128x64 tile, 256 threads = 8 warps (4x2).
// EPI: 0 plain fp32 out; 1 half plain (Q,K); 2 half key-pair interleaved (V).
#define GBK 64
#define BKP 72
#define G_TILE (128*BKP)
#define GSMEM (4*G_TILE*2)          // 73728 B

template<int EPI>
__device__ __forceinline__ void gemm_body(
    const __half* __restrict__ A, const __half* __restrict__ Bt,
    const float* __restrict__ bias, void* Cptr,
    int M, int N, int K, int bm, int bn, __half* gsm)
{
    __half (*As)[128][BKP] = (__half(*)[128][BKP])gsm;
    __half (*Bs)[128][BKP] = (__half(*)[128][BKP])(gsm + 2 * G_TILE);

    const int tid = threadIdx.x;
    const int lane = tid & 31, wid = tid >> 5;
    const int gid = lane >> 2, tig = lane & 3;
    const int wm = wid >> 1, wn = wid & 1;

    float acc[2][8][4];
#pragma unroll
    for (int i = 0; i < 2; i++)
#pragma unroll
        for (int j = 0; j < 8; j++)
#pragma unroll
            for (int v = 0; v < 4; v++) acc[i][j][v] = 0.f;

    const int T = K / GBK;

    auto load_stage = [&](int st, int t) {
        const int k0 = t * GBK;
#pragma unroll
        for (int u = 0; u < 4; u++) {
            int id = tid + u * 256;
            int r = id >> 3, c = id & 7;
            cp_async16(&As[st][r][c * 8], A  + (size_t)(bm + r) * K + k0 + c * 8);
            cp_async16(&Bs[st][r][c * 8], Bt + (size_t)(bn + r) * K + k0 + c * 8);
        }
    };

    load_stage(0, 0);
    CP_COMMIT;

    for (int t = 0; t < T; t++) {
        const int st = t & 1;
        CP_WAIT0;
        __syncthreads();
        if (t + 1 < T) {
            load_stage(st ^ 1, t + 1);
            CP_COMMIT;
        }

#pragma unroll
        for (int kk = 0; kk < GBK; kk += 16) {
            unsigned a[2][4];
#pragma unroll
            for (int mt = 0; mt < 2; mt++) {
                int r = wm * 32 + mt * 16 + gid;
                a[mt][0] = ldu32(&As[st][r][kk + 2 * tig]);
                a[mt][1] = ldu32(&As[st][r + 8][kk + 2 * tig]);
                a[mt][2] = ldu32(&As[st][r][kk + 2 * tig + 8]);
                a[mt][3] = ldu32(&As[st][r + 8][kk + 2 * tig + 8]);
            }
#pragma unroll
            for (int nt = 0; nt < 8; nt++) {
                int c = wn * 64 + nt * 8 + gid;
                unsigned b0 = ldu32(&Bs[st][c][kk + 2 * tig]);
                unsigned b1 = ldu32(&Bs[st][c][kk + 2 * tig + 8]);
                mma_f16(acc[0][nt], a[0], b0, b1);
                mma_f16(acc[1][nt], a[1], b0, b1);
            }
        }
    }

#pragma unroll
    for (int mt = 0; mt < 2; mt++) {
        int rbase = bm + wm * 32 + mt * 16 + gid;
#pragma unroll
        for (int nt = 0; nt < 8; nt++) {
            int c = bn + wn * 64 + nt * 8 + 2 * tig;
            float bx = bias[c], by = bias[c + 1];
            float v0 = acc[mt][nt][0] + bx, v1 = acc[mt][nt][1] + by;
            float v2 = acc[mt][nt][2] + bx, v3 = acc[mt][nt][3] + by;
            if (EPI == 0) {
                float* C = (float*)Cptr;
                *(float2*)&C[(size_t)rbase * N + c] = make_float2(v0, v1);
                *(float2*)&C[(size_t)(rbase + 8) * N + c] = make_float2(v2, v3);
            } else if (EPI == 1) {
                __half* C = (__half*)Cptr;
                *(__half2*)&C[(size_t)rbase * N + c] = __floats2half2_rn(v0, v1);
                *(__half2*)&C[(size_t)(rbase + 8) * N + c] = __floats2half2_rn(v2, v3);
            } else {
                __half* C = (__half*)Cptr;
#pragma unroll
                for (int rr = 0; rr < 2; rr++) {
                    int r = rbase + rr * 8;
                    size_t base = (size_t)(r & ~1) * N + (r & 1);
                    float a0 = rr ? v2 : v0, a1 = rr ? v3 : v1;
                    C[base + (size_t)c * 2] = __float2half(a0);
                    C[base + (size_t)(c + 1) * 2] = __float2half(a1);
                }
            }
        }
    }
}

// fused Q+K+V projection: grid (24, 32).
// bx<16 -> Q tile (EPI1, N=HID); bx in [16,20) -> K (EPI1, N=KVD); else V (EPI2, N=KVD)
__global__ __launch_bounds__(256, 2) void gemm_h_qkv(
    const __half* __restrict__ A,
    const __half* __restrict__ Wq, const __half* __restrict__ Wk,
    const __half* __restrict__ Wv,
    const float* __restrict__ bq, const float* __restrict__ bk,
    const float* __restrict__ bv,
    __half* __restrict__ Cq, __half* __restrict__ Ck, __half* __restrict__ Cv,
    int M, int K)
{
    extern __shared__ __half gsm[];
    const int bx = blockIdx.x;
    const int bm = blockIdx.y * 128;
    if (bx < 16) {
        gemm_body<1>(A, Wq, bq, (void*)Cq, M, HID, K, bm, bx * 128, gsm);
    } else if (bx < 20) {
        gemm_body<1>(A, Wk, bk, (void*)Ck, M, KVD, K, bm, (bx - 16) * 128, gsm);
    } else {
        gemm_body<2>(A, Wv, bv, (void*)Cv, M, KVD, K, bm, (bx - 20) * 128, gsm);
    }
}

template<int EPI>
__global__ __launch_bounds__(256, 2) void gemm_h(
    const __half* __restrict__ A, const __half* __restrict__ Bt,
    const float* __restrict__ bias, void* C, int M, int N, int K)
{
    extern __shared__ __half gsm[];
    gemm_body<EPI>(A, Bt, bias, C, M, N, K,
                   blockIdx.y * 128, blockIdx.x * 128, gsm);
}

// ================= Flash attention (fp16, BK=64, register-resident Q & P) ==========
#define AQP 136                        // 68 words = 4 mod 8
#define AKP 136
#define AVL 272                        // V pair-line: 256 halves + 16 pad
#define OQ_  0
#define OKs  (64*AQP)                  // 8704 halves
#define OVs  (OKs + 2*64*AKP)          // +17408
#define OMs  (OVs + 2*32*AVL)          // +17408 -> 43520 halves
#define ASMEM (OMs*2 + 2*64*4)         // 87552 B -> 2 CTAs/SM

__global__ __launch_bounds__(128, 2) void attn_h(const int* __restrict__ mask)
{
    extern __shared__ __half sm[];
    __half (*Qs)[AQP]     = (__half(*)[AQP])(sm + OQ_);
    __half (*Ks)[64][AKP] = (__half(*)[64][AKP])(sm + OKs);
    __half (*Vs)[32][AVL] = (__half(*)[32][AVL])(sm + OVs);
    int (*Ms)[64]         = (int(*)[64])(sm + OMs);

    const int tid = threadIdx.x;
    const int w = tid >> 5, lane = tid & 31;
    const int gid = lane >> 2, tig = lane & 3;
    const int qt = blockIdx.x, h = blockIdx.y, b = blockIdx.z;
    const int g = h % GROUPS;
    const int q0 = qt * 64;

    const float scale = 0.08838834764831845f;  // 1/sqrt(128)
    const __half* Qg = g_Q + (size_t)(b * SEQ + q0) * HID + h * HDIM;
    const __half* Kg0 = g_K + (size_t)(b * SEQ) * KVD + g * HDIM;
    const __half* Vg0 = g_V + (size_t)(b * SEQ) * KVD;   // interleaved
    const int*    Mg0 = mask + b * SEQ;

    auto issue_kv = [&](int st, int kt) {
        const int k0 = kt * 64;
#pragma unroll
        for (int u = 0; u < 8; u++) {
            int id = tid + u * 128;
            int r = id >> 4, c = id & 15;
            cp_async16(&Ks[st][r][c * 8], Kg0 + (size_t)(k0 + r) * KVD + c * 8);
            int line = id >> 5, cc = id & 31;
            const __half* src = Vg0 + (size_t)(k0 + 2 * line) * KVD + g * 256 + cc * 8;
            cp_async16(&Vs[st][line][cc * 8], src);
        }
        if (tid < 16) cp_async16(&Ms[st][tid * 4], Mg0 + k0 + tid * 4);
    };

    issue_kv(0, 0);
    CP_COMMIT;

    // Q prologue: load half, scale in fp32, re-round to half, stage in smem
#pragma unroll
    for (int u = 0; u < 8; u++) {
        int idx = tid + u * 128;
        int r = idx >> 4, c8 = idx & 15;
        uint4 raw = *(const uint4*)(Qg + (size_t)r * HID + c8 * 8);
        __half2* hp = (__half2*)&raw;
        __half2 o[4];
#pragma unroll
        for (int j = 0; j < 4; j++) {
            float2 f = __half22float2(hp[j]);
            o[j] = __floats2half2_rn(f.x * scale, f.y * scale);
        }
        *(uint4*)&Qs[r][c8 * 8] = *(uint4*)o;
    }
    __syncthreads();   // Qs visible across warps

    // hoist Q fragments to registers
    const int r = w * 16 + gid;
    unsigned qa[8][4];
#pragma unroll
    for (int ks = 0; ks < 8; ks++) {
        const int kk = ks * 16;
        qa[ks][0] = ldu32(&Qs[r][kk + 2 * tig]);
        qa[ks][1] = ldu32(&Qs[r + 8][kk + 2 * tig]);
        qa[ks][2] = ldu32(&Qs[r][kk + 2 * tig + 8]);
        qa[ks][3] = ldu32(&Qs[r + 8][kk + 2 * tig + 8]);
    }

    float m_run[2] = {-1e30f, -1e30f};
    float l_run[2] = {0.f, 0.f};
    float o_acc[16][4];
#pragma unroll
    for (int nt = 0; nt < 16; nt++)
#pragma unroll
        for (int v = 0; v < 4; v++) o_acc[nt][v] = 0.f;

    for (int kt = 0; kt < SEQ / 64; kt++) {
        const int st = kt & 1;
        CP_WAIT0;
        __syncthreads();
        if (kt + 1 < SEQ / 64) {
            issue_kv(st ^ 1, kt + 1);
            CP_COMMIT;
        }

        // ---- S = Q @ K^T (16 rows x 64 keys per warp) ----
        float s[8][4];
#pragma unroll
        for (int nt = 0; nt < 8; nt++)
#pragma unroll
            for (int v = 0; v < 4; v++) s[nt][v] = 0.f;

#pragma unroll
        for (int ks = 0; ks < 8; ks++) {
            const int kk = ks * 16;
#pragma unroll
            for (int nt = 0; nt < 8; nt++) {
                int key = nt * 8 + gid;
                unsigned b0 = ldu32(&Ks[st][key][kk + 2 * tig]);
                unsigned b1 = ldu32(&Ks[st][key][kk + 2 * tig + 8]);
                mma_f16(s[nt], qa[ks], b0, b1);
            }
        }

        // ---- mask ----
#pragma unroll
        for (int nt = 0; nt < 8; nt++) {
            int c = nt * 8 + 2 * tig;
            if (Ms[st][c] == 0)     { s[nt][0] = -1e30f; s[nt][2] = -1e30f; }
            if (Ms[st][c + 1] == 0) { s[nt][1] = -1e30f; s[nt][3] = -1e30f; }
        }

        // ---- online softmax (row halves gid, gid+8) ----
#pragma unroll
        for (int hh = 0; hh < 2; hh++) {
            float mx = -1e30f;
#pragma unroll
            for (int nt = 0; nt < 8; nt++)
                mx = fmaxf(mx, fmaxf(s[nt][2 * hh], s[nt][2 * hh + 1]));
            mx = fmaxf(mx, __shfl_xor_sync(0xffffffffu, mx, 1));
            mx = fmaxf(mx, __shfl_xor_sync(0xffffffffu, mx, 2));
            float mnew = fmaxf(m_run[hh], mx);
            float corr = __expf(m_run[hh] - mnew);
            float sum = 0.f;
#pragma unroll
            for (int nt = 0; nt < 8; nt++) {
                float p0 = __expf(s[nt][2 * hh] - mnew);
                float p1 = __expf(s[nt][2 * hh + 1] - mnew);
                s[nt][2 * hh] = p0; s[nt][2 * hh + 1] = p1;
                sum += p0 + p1;
            }
            sum += __shfl_xor_sync(0xffffffffu, sum, 1);
            sum += __shfl_xor_sync(0xffffffffu, sum, 2);
            l_run[hh] = l_run[hh] * corr + sum;
            if (mnew > m_run[hh]) {
                m_run[hh] = mnew;
#pragma unroll
                for (int nt = 0; nt < 16; nt++) {
                    o_acc[nt][2 * hh] *= corr;
                    o_acc[nt][2 * hh + 1] *= corr;
                }
            }
        }

        // ---- O += P @ V : P taken directly from S registers ----
#pragma unroll
        for (int ks = 0; ks < 4; ks++) {
            const int kk = ks * 16;
            unsigned pa[4];
            pa[0] = packh2(s[2 * ks][0], s[2 * ks][1]);
            pa[1] = packh2(s[2 * ks][2], s[2 * ks][3]);
            pa[2] = packh2(s[2 * ks + 1][0], s[2 * ks + 1][1]);
            pa[3] = packh2(s[2 * ks + 1][2], s[2 * ks + 1][3]);
            const int l0 = kk / 2 + tig;
            const int l1 = kk / 2 + tig + 4;
#pragma unroll
            for (int nt = 0; nt < 16; nt++) {
                int n = nt * 8 + gid;
                unsigned b0 = ldu32(&Vs[st][l0][n * 2]);
                unsigned b1 = ldu32(&Vs[st][l1][n * 2]);
                mma_f16(o_acc[nt], pa, b0, b1);
            }
        }
    }

    // ---- epilogue: O /= l, half, plain layout ----
    __half* Og = g_O + (size_t)(b * SEQ + q0) * HID + h * HDIM;
    const float i0 = 1.f / l_run[0], i1 = 1.f / l_run[1];
#pragma unroll
    for (int nt = 0; nt < 16; nt++) {
        int c = nt * 8 + 2 * tig;
        *(__half2*)&Og[(size_t)r * HID + c] =
            __floats2half2_rn(o_acc[nt][0] * i0, o_acc[nt][1] * i0);
        *(__half2*)&Og[(size_t)(r + 8) * HID + c] =
            __floats2half2_rn(o_acc[nt][2] * i1, o_acc[nt][3] * i1);
    }
}

// ================= launch =================
extern "C" void kernel_launch(void* const* d_in, const int* in_sizes, int n_in,
                              void* d_out, int out_size)
{
    const float* X    = (const float*)d_in[0];
    const int*   mask = (const int*)  d_in[1];
    const float* Wq   = (const float*)d_in[2];
    const float* bq   = (const float*)d_in[3];
    const float* Wk   = (const float*)d_in[4];
    const float* bk   = (const float*)d_in[5];
    const float* Wv   = (const float*)d_in[6];
    const float* bv   = (const float*)d_in[7];
    const float* Wo   = (const float*)d_in[8];
    const float* bo   = (const float*)d_in[9];
    float* out = (float*)d_out;

    __half *Qp, *Kp, *Vp, *Op, *Xh, *Wqt, *Wkt, *Wvt, *Wot;
    cudaGetSymbolAddress((void**)&Qp, g_Q);
    cudaGetSymbolAddress((void**)&Kp, g_K);
    cudaGetSymbolAddress((void**)&Vp, g_V);
    cudaGetSymbolAddress((void**)&Op, g_O);
    cudaGetSymbolAddress((void**)&Xh, g_Xh);
    cudaGetSymbolAddress((void**)&Wqt, g_Wqt);
    cudaGetSymbolAddress((void**)&Wkt, g_Wkt);
    cudaGetSymbolAddress((void**)&Wvt, g_Wvt);
    cudaGetSymbolAddress((void**)&Wot, g_Wot);

    cudaFuncSetAttribute(gemm_h<0>, cudaFuncAttributeMaxDynamicSharedMemorySize, GSMEM);
    cudaFuncSetAttribute(gemm_h_qkv, cudaFuncAttributeMaxDynamicSharedMemorySize, GSMEM);
    cudaFuncSetAttribute(attn_h, cudaFuncAttributeMaxDynamicSharedMemorySize, ASMEM);

    // fused prep: X cast + 4 weight transposes in one launch
    prep_all<<<14336, 256>>>(X, Wq, Wk, Wv, Wo, Xh, Wqt, Wkt, Wvt, Wot);

    // fused Q+K+V projections: one 768-CTA launch (2.6 full waves, single tail)
    gemm_h_qkv<<<dim3(24, MROWS / 128), dim3(256), GSMEM>>>(
        Xh, Wqt, Wkt, Wvt, bq, bk, bv, Qp, Kp, Vp, MROWS, HID);

    attn_h<<<dim3(SEQ / 64, HEADS, BATCH), dim3(128), ASMEM>>>(mask);

    gemm_h<0><<<dim3(HID / 128, MROWS / 128), dim3(256), GSMEM>>>(
        Op, Wot, bo, (void*)out, MROWS, HID, HID);
}